// round 7
// baseline (speedup 1.0000x reference)
#include <cuda_runtime.h>
#include <cuda_fp16.h>
#include <math.h>
#include <stdint.h>

// ---------------------------------------------------------------------------
// Problem constants
// ---------------------------------------------------------------------------
#define NB   4
#define LL   4096
#define SEQS 4096
#define CC   512
#define NH   8
#define HD   64
#define C2   1024
#define NTOK (NB * LL)          // 16384
#define EPS_Z 1e-6f
#define LN_EPS 1e-5f

// ---------------------------------------------------------------------------
// Scratch (device globals; no allocation allowed)
// ---------------------------------------------------------------------------
__device__ __align__(16) float g_Q [(size_t)NTOK * CC];
__device__ __align__(16) float g_K [(size_t)NTOK * CC];
__device__ __align__(16) float g_V [(size_t)NTOK * CC];
__device__ __align__(16) float g_KV[NB * NH * HD * HD];
__device__ __align__(16) float g_Ks[NB * NH * HD];
__device__ __align__(16) float g_M1[(size_t)NTOK * CC];
__device__ __align__(16) float g_M2[(size_t)NTOK * CC];

// split fp16 (hi/lo) activations; weights use hi only
__device__ __align__(16) __half g_xh[(size_t)NTOK * CC], g_xl[(size_t)NTOK * CC];
__device__ __align__(16) __half g_yh[(size_t)NTOK * CC], g_yl[(size_t)NTOK * CC];
__device__ __align__(16) __half g_Wqh[CC * CC];
__device__ __align__(16) __half g_Wkh[CC * CC];
__device__ __align__(16) __half g_Wvh[CC * CC];
__device__ __align__(16) __half g_Wmh[CC * CC];
__device__ __align__(16) __half g_W1h[C2 * C2];
__device__ __align__(16) __half g_W2h[CC * C2];
__device__ __align__(16) __half g_Mh  [(size_t)NTOK * CC], g_Ml  [(size_t)NTOK * CC];
__device__ __align__(16) __half g_mlnh[(size_t)NTOK * CC], g_mlnl[(size_t)NTOK * CC];
__device__ __align__(16) __half g_H1h [(size_t)NTOK * C2], g_H1l [(size_t)NTOK * C2];

// ---------------------------------------------------------------------------
// PTX helpers
// ---------------------------------------------------------------------------
__device__ __forceinline__ uint32_t smem_u32(const void* p)
{
    uint32_t a;
    asm("{ .reg .u64 t; cvta.to.shared.u64 t, %1; cvt.u32.u64 %0, t; }"
        : "=r"(a) : "l"(p));
    return a;
}

__device__ __forceinline__ void cpasync16(uint32_t dst, const void* src)
{
    asm volatile("cp.async.cg.shared.global [%0], [%1], 16;"
                 :: "r"(dst), "l"(src) : "memory");
}
__device__ __forceinline__ void cp_commit()
{
    asm volatile("cp.async.commit_group;" ::: "memory");
}
template <int N>
__device__ __forceinline__ void cp_wait()
{
    asm volatile("cp.async.wait_group %0;" :: "n"(N) : "memory");
}

__device__ __forceinline__ void ldm_x4(uint32_t& r0, uint32_t& r1,
                                       uint32_t& r2, uint32_t& r3, uint32_t a)
{
    asm volatile("ldmatrix.sync.aligned.m8n8.x4.shared.b16 {%0,%1,%2,%3}, [%4];"
                 : "=r"(r0), "=r"(r1), "=r"(r2), "=r"(r3) : "r"(a));
}

__device__ __forceinline__ void mma16816(float* c, const uint32_t* a,
                                         const uint32_t* b)
{
    asm volatile(
        "mma.sync.aligned.m16n8k16.row.col.f32.f16.f16.f32 "
        "{%0,%1,%2,%3}, {%4,%5,%6,%7}, {%8,%9}, {%0,%1,%2,%3};"
        : "+f"(c[0]), "+f"(c[1]), "+f"(c[2]), "+f"(c[3])
        : "r"(a[0]), "r"(a[1]), "r"(a[2]), "r"(a[3]), "r"(b[0]), "r"(b[1]));
}

// ---------------------------------------------------------------------------
// Mega split: fp32 -> fp16 hi/lo (lo null -> hi only for weights)
// ---------------------------------------------------------------------------
#define NSPLIT 8
struct SplitJobs {
    const float* src[NSPLIT];
    __half* hi[NSPLIT];
    __half* lo[NSPLIT];
    int n4[NSPLIT];
    int blkoff[NSPLIT + 1];
};

__global__ void __launch_bounds__(256)
split_all(SplitJobs J)
{
    int b = blockIdx.x;
    int j = 0;
#pragma unroll
    for (int t = 0; t < NSPLIT - 1; t++)
        if (b >= J.blkoff[t + 1]) j = t + 1;
    const int i = (b - J.blkoff[j]) * 256 + threadIdx.x;
    if (i >= J.n4[j]) return;
    float4 v = ((const float4*)J.src[j])[i];
    __half h0 = __float2half_rn(v.x);
    __half h1 = __float2half_rn(v.y);
    __half h2 = __float2half_rn(v.z);
    __half h3 = __float2half_rn(v.w);
    ((__half2*)J.hi[j])[i * 2 + 0] = __half2(h0, h1);
    ((__half2*)J.hi[j])[i * 2 + 1] = __half2(h2, h3);
    if (J.lo[j]) {
        __half l0 = __float2half_rn(v.x - __half2float(h0));
        __half l1 = __float2half_rn(v.y - __half2float(h1));
        __half l2 = __float2half_rn(v.z - __half2float(h2));
        __half l3 = __float2half_rn(v.w - __half2float(h3));
        ((__half2*)J.lo[j])[i * 2 + 0] = __half2(l0, l1);
        ((__half2*)J.lo[j])[i * 2 + 1] = __half2(l2, l3);
    }
}

// ---------------------------------------------------------------------------
// fp16 2-pass HMMA GEMM, BK=64 fp32-K per chunk, dual A-source.
// C[m,n] = epi( scale * sum_k A[m,k]*B[n,k] ); A split hi/lo, B hi only.
// Tile 128x128, 2-stage cp.async, 8 warps 2x4 (warp tile 64x32).
// smem row = 64 halves (128B) + 16B pad = 144B; +4 banks/row -> conflict-free.
// EPI: 0 = scale -> f32, 1 = elu+1 -> f32, 2 = relu -> fp16 hi/lo
// ---------------------------------------------------------------------------
#define ROWB   144
#define MATB   (128 * ROWB)       // 18432 B
#define STAGEB (3 * MATB)         // 55296 B (Ah, Al, Bh)
#define SMEM_GEMM (2 * STAGEB)    // 110592 B

template <int EPI>
__global__ void __launch_bounds__(256, 2)
hmma_gemm(const __half* __restrict__ A1h, const __half* __restrict__ A1l,
          const __half* __restrict__ A2h, const __half* __restrict__ A2l,
          const __half* __restrict__ Bh,
          float* __restrict__ Cf, __half* __restrict__ Ch,
          __half* __restrict__ Cl, int N, int K, int kSplit,
          size_t sA1b, size_t sA2b, float scale)
{
    extern __shared__ __align__(16) uint8_t dynsm[];
    const uint32_t sbase = smem_u32(dynsm);

    const int tid  = threadIdx.x;
    const int wid  = tid >> 5;
    const int lane = tid & 31;
    const int wr   = wid >> 2;
    const int wc   = wid & 3;
    const int bx   = blockIdx.x;
    const int by   = blockIdx.y;

    // cp.async geometry: row = tid>>1 (0..127), cb = (tid&1)*64, 4x16B each
    const int rowL = tid >> 1;
    const int cb   = (tid & 1) * 64;
    const size_t sBb = (size_t)K * 2;

    const char* gA1h = (const char*)A1h + (size_t)(by * 128 + rowL) * sA1b + cb;
    const char* gA1l = (const char*)A1l + (size_t)(by * 128 + rowL) * sA1b + cb;
    const char* gA2h = (const char*)A2h + (size_t)(by * 128 + rowL) * sA2b + cb;
    const char* gA2l = (const char*)A2l + (size_t)(by * 128 + rowL) * sA2b + cb;
    const char* gBh0 = (const char*)Bh  + (size_t)(bx * 128 + rowL) * sBb + cb;

    const uint32_t dst0 = (uint32_t)(rowL * ROWB + cb);

    auto issue = [&](int stage, int chunk) {
        const uint32_t s = sbase + stage * STAGEB;
        const char *ah, *al; size_t o;
        if (chunk < kSplit) { ah = gA1h; al = gA1l; o = (size_t)chunk * 128; }
        else { ah = gA2h; al = gA2l; o = (size_t)(chunk - kSplit) * 128; }
        const size_t ob = (size_t)chunk * 128;
#pragma unroll
        for (int j = 0; j < 4; j++) {
            cpasync16(s + 0 * MATB + dst0 + j * 16, ah + o + j * 16);
            cpasync16(s + 1 * MATB + dst0 + j * 16, al + o + j * 16);
            cpasync16(s + 2 * MATB + dst0 + j * 16, gBh0 + ob + j * 16);
        }
        cp_commit();
    };

    const uint32_t aRow = (uint32_t)(wr * 64 + (lane & 15));
    const uint32_t aCol = (uint32_t)((lane >> 4) << 4);
    const uint32_t bRow = (uint32_t)(wc * 32 + (lane & 7) + ((lane >> 4) << 3));
    const uint32_t bCol = (uint32_t)(((lane >> 3) & 1) << 4);

    float acc[4][4][4];
#pragma unroll
    for (int i = 0; i < 4; i++)
#pragma unroll
        for (int j = 0; j < 4; j++)
#pragma unroll
            for (int q = 0; q < 4; q++) acc[i][j][q] = 0.f;

    const int nch = K / 64;
    issue(0, 0);

    for (int c = 0; c < nch; c++) {
        if (c + 1 < nch) { issue((c + 1) & 1, c + 1); cp_wait<1>(); }
        else             { cp_wait<0>(); }
        __syncthreads();

        const uint32_t s  = sbase + (c & 1) * STAGEB;
        const uint32_t pAh = s + 0 * MATB, pAl = s + 1 * MATB, pBh = s + 2 * MATB;

#pragma unroll
        for (int ks = 0; ks < 4; ks++) {
            const uint32_t kb = (uint32_t)(ks * 32);

            uint32_t ah[4][4], bh[2][4];
#pragma unroll
            for (int mi = 0; mi < 4; mi++)
                ldm_x4(ah[mi][0], ah[mi][1], ah[mi][2], ah[mi][3],
                       pAh + (aRow + mi * 16) * ROWB + kb + aCol);
#pragma unroll
            for (int ng = 0; ng < 2; ng++)
                ldm_x4(bh[ng][0], bh[ng][1], bh[ng][2], bh[ng][3],
                       pBh + (bRow + ng * 16) * ROWB + kb + bCol);
#pragma unroll
            for (int mi = 0; mi < 4; mi++)
#pragma unroll
                for (int ni = 0; ni < 4; ni++)
                    mma16816(acc[mi][ni], ah[mi], &bh[ni >> 1][(ni & 1) * 2]);

            // lo(A) * hi(B)
#pragma unroll
            for (int mi = 0; mi < 4; mi++) {
                uint32_t al[4];
                ldm_x4(al[0], al[1], al[2], al[3],
                       pAl + (aRow + mi * 16) * ROWB + kb + aCol);
#pragma unroll
                for (int ni = 0; ni < 4; ni++)
                    mma16816(acc[mi][ni], al, &bh[ni >> 1][(ni & 1) * 2]);
            }
        }
        __syncthreads();
    }

    // ---- epilogue
#pragma unroll
    for (int mi = 0; mi < 4; mi++) {
#pragma unroll
        for (int ni = 0; ni < 4; ni++) {
            const int r = by * 128 + wr * 64 + mi * 16 + (lane >> 2);
            const int cn = bx * 128 + wc * 32 + ni * 8 + (lane & 3) * 2;
            float v0 = acc[mi][ni][0] * scale;
            float v1 = acc[mi][ni][1] * scale;
            float v2 = acc[mi][ni][2] * scale;
            float v3 = acc[mi][ni][3] * scale;
            if (EPI == 1) {
                v0 = (v0 > 0.f) ? (v0 + 1.f) : expf(v0);
                v1 = (v1 > 0.f) ? (v1 + 1.f) : expf(v1);
                v2 = (v2 > 0.f) ? (v2 + 1.f) : expf(v2);
                v3 = (v3 > 0.f) ? (v3 + 1.f) : expf(v3);
            }
            if (EPI == 2) {
                v0 = fmaxf(v0, 0.f); v1 = fmaxf(v1, 0.f);
                v2 = fmaxf(v2, 0.f); v3 = fmaxf(v3, 0.f);
                __half h0 = __float2half_rn(v0), h1 = __float2half_rn(v1);
                __half h2 = __float2half_rn(v2), h3 = __float2half_rn(v3);
                *(__half2*)(Ch + (size_t)r * N + cn) = __half2(h0, h1);
                *(__half2*)(Ch + (size_t)(r + 8) * N + cn) = __half2(h2, h3);
                *(__half2*)(Cl + (size_t)r * N + cn) =
                    __half2(__float2half_rn(v0 - __half2float(h0)),
                            __float2half_rn(v1 - __half2float(h1)));
                *(__half2*)(Cl + (size_t)(r + 8) * N + cn) =
                    __half2(__float2half_rn(v2 - __half2float(h2)),
                            __float2half_rn(v3 - __half2float(h3)));
            } else {
                *(float2*)(Cf + (size_t)r * N + cn) = make_float2(v0, v1);
                *(float2*)(Cf + (size_t)(r + 8) * N + cn) = make_float2(v2, v3);
            }
        }
    }
}

// ---------------------------------------------------------------------------
// Zero KV / Ksum accumulators
// ---------------------------------------------------------------------------
__global__ void zero_kv_kernel()
{
    int i = blockIdx.x * blockDim.x + threadIdx.x;
    if (i < NB * NH * HD * HD) g_KV[i] = 0.f;
    if (i < NB * NH * HD)      g_Ks[i] = 0.f;
}

// ---------------------------------------------------------------------------
// KV[n,h,d,v] = sum_s K[n,s,h,d]*V[n,s,h,v] ; Ksum[n,h,d] = sum_s K[n,s,h,d]
// ---------------------------------------------------------------------------
#define KV_SPLIT 16
__global__ void __launch_bounds__(256)
kv_kernel()
{
    const int n = blockIdx.z, h = blockIdx.y, sp = blockIdx.x;
    const int SPS = SEQS / KV_SPLIT;
    const int s0  = sp * SPS;

    __shared__ float Ksm[16][HD];
    __shared__ float Vsm[16][HD];

    const int tid = threadIdx.x;
    const int d0  = (tid >> 4) * 4;
    const int v0  = (tid & 15) * 4;
    const int lr  = tid >> 4;
    const int lq  = (tid & 15) * 4;

    float acc[4][4];
#pragma unroll
    for (int i = 0; i < 4; i++)
#pragma unroll
        for (int j = 0; j < 4; j++) acc[i][j] = 0.f;
    float ksacc[4] = {0.f, 0.f, 0.f, 0.f};

    for (int sc = 0; sc < SPS; sc += 16) {
        const size_t base = ((size_t)(n * SEQS + s0 + sc + lr)) * CC + h * HD + lq;
        float4 kv4 = *(const float4*)(g_K + base);
        Ksm[lr][lq + 0] = kv4.x; Ksm[lr][lq + 1] = kv4.y;
        Ksm[lr][lq + 2] = kv4.z; Ksm[lr][lq + 3] = kv4.w;
        float4 vv4 = *(const float4*)(g_V + base);
        Vsm[lr][lq + 0] = vv4.x; Vsm[lr][lq + 1] = vv4.y;
        Vsm[lr][lq + 2] = vv4.z; Vsm[lr][lq + 3] = vv4.w;
        __syncthreads();

#pragma unroll
        for (int s = 0; s < 16; s++) {
            float a[4], b[4];
#pragma unroll
            for (int i = 0; i < 4; i++) a[i] = Ksm[s][d0 + i];
#pragma unroll
            for (int j = 0; j < 4; j++) b[j] = Vsm[s][v0 + j];
#pragma unroll
            for (int i = 0; i < 4; i++)
#pragma unroll
                for (int j = 0; j < 4; j++) acc[i][j] = fmaf(a[i], b[j], acc[i][j]);
            if (v0 == 0) {
#pragma unroll
                for (int i = 0; i < 4; i++) ksacc[i] += a[i];
            }
        }
        __syncthreads();
    }

    float* KVp = g_KV + (size_t)(n * NH + h) * HD * HD;
#pragma unroll
    for (int i = 0; i < 4; i++)
#pragma unroll
        for (int j = 0; j < 4; j++)
            atomicAdd(&KVp[(d0 + i) * HD + v0 + j], acc[i][j]);
    if (v0 == 0) {
        float* Kp = g_Ks + (n * NH + h) * HD;
#pragma unroll
        for (int i = 0; i < 4; i++) atomicAdd(&Kp[d0 + i], ksacc[i]);
    }
}

// ---------------------------------------------------------------------------
// message: one thread per l-row, KV broadcast from smem, no inner syncs.
// ---------------------------------------------------------------------------
__global__ void __launch_bounds__(128)
msg_kernel()
{
    const int n = blockIdx.z, h = blockIdx.y, lt = blockIdx.x;
    __shared__ float KVs[HD][HD];
    __shared__ float Kss[HD];

    const int tid = threadIdx.x;
    const size_t kvbase = (size_t)(n * NH + h) * HD * HD;
    for (int idx = tid; idx < HD * HD; idx += 128)
        KVs[idx >> 6][idx & 63] = g_KV[kvbase + idx];
    if (tid < HD) Kss[tid] = g_Ks[(n * NH + h) * HD + tid];
    __syncthreads();

    const int l = lt * 128 + tid;
    const size_t qbase = ((size_t)(n * LL + l)) * CC + h * HD;

    float acc[HD];
#pragma unroll
    for (int v = 0; v < HD; v++) acc[v] = 0.f;
    float zden = EPS_Z;

#pragma unroll
    for (int d0 = 0; d0 < HD; d0 += 4) {
        const float4 q4 = *(const float4*)(g_Q + qbase + d0);
        const float qv[4] = {q4.x, q4.y, q4.z, q4.w};
#pragma unroll
        for (int dd = 0; dd < 4; dd++) {
            const float q = qv[dd];
            zden = fmaf(q, Kss[d0 + dd], zden);
#pragma unroll
            for (int v0 = 0; v0 < HD; v0 += 4) {
                const float4 kv = *(const float4*)&KVs[d0 + dd][v0];
                acc[v0 + 0] = fmaf(q, kv.x, acc[v0 + 0]);
                acc[v0 + 1] = fmaf(q, kv.y, acc[v0 + 1]);
                acc[v0 + 2] = fmaf(q, kv.z, acc[v0 + 2]);
                acc[v0 + 3] = fmaf(q, kv.w, acc[v0 + 3]);
            }
        }
    }

    const float zs = (float)SEQS / zden;
#pragma unroll
    for (int v = 0; v < HD; v += 2) {
        const float r0 = acc[v] * zs, r1 = acc[v + 1] * zs;
        const __half h0 = __float2half_rn(r0);
        const __half h1 = __float2half_rn(r1);
        *(__half2*)(g_Mh + qbase + v) = __half2(h0, h1);
        *(__half2*)(g_Ml + qbase + v) =
            __half2(__float2half_rn(r0 - __half2float(h0)),
                    __float2half_rn(r1 - __half2float(h1)));
    }
}

// ---------------------------------------------------------------------------
// Block reduction helper (256 threads)
// ---------------------------------------------------------------------------
__device__ __forceinline__ float block_reduce_sum(float v)
{
    __shared__ float red[8];
    const int lane = threadIdx.x & 31, w = threadIdx.x >> 5;
#pragma unroll
    for (int o = 16; o; o >>= 1) v += __shfl_down_sync(0xffffffffu, v, o);
    if (lane == 0) red[w] = v;
    __syncthreads();
    float t = (threadIdx.x < 8) ? red[threadIdx.x] : 0.f;
    if (w == 0) {
#pragma unroll
        for (int o = 4; o; o >>= 1) t += __shfl_down_sync(0xffu, t, o);
        if (lane == 0) red[0] = t;
    }
    __syncthreads();
    float r = red[0];
    __syncthreads();
    return r;
}

// ---------------------------------------------------------------------------
// LN(M1) -> fp16 hi/lo (message half of the concat). One block per row.
// ---------------------------------------------------------------------------
__global__ void __launch_bounds__(256)
ln_split_kernel(const float* __restrict__ g, const float* __restrict__ b)
{
    const int row = blockIdx.x;
    __shared__ float buf[CC];
    const float* mr = g_M1 + (size_t)row * CC;
    const int tid = threadIdx.x;

    float s = 0.f;
    for (int c = tid; c < CC; c += 256) { float v = mr[c]; buf[c] = v; s += v; }
    const float mean = block_reduce_sum(s) * (1.f / CC);

    float vs = 0.f;
    for (int c = tid; c < CC; c += 256) { float d = buf[c] - mean; vs += d * d; }
    const float var  = block_reduce_sum(vs) * (1.f / CC);
    const float rstd = rsqrtf(var + LN_EPS);

    for (int c = tid; c < CC; c += 256) {
        const float lv = (buf[c] - mean) * rstd * g[c] + b[c];
        const __half h = __float2half_rn(lv);
        g_mlnh[(size_t)row * CC + c] = h;
        g_mlnl[(size_t)row * CC + c] = __float2half_rn(lv - __half2float(h));
    }
}

// ---------------------------------------------------------------------------
// out = x + LN(M2). One block per row.
// ---------------------------------------------------------------------------
__global__ void __launch_bounds__(256)
ln_add_kernel(const float* __restrict__ x,
              const float* __restrict__ g, const float* __restrict__ b,
              float* __restrict__ out)
{
    const int row = blockIdx.x;
    __shared__ float buf[CC];
    const float* mr = g_M2 + (size_t)row * CC;
    const int tid = threadIdx.x;

    float s = 0.f;
    for (int c = tid; c < CC; c += 256) { float v = mr[c]; buf[c] = v; s += v; }
    const float mean = block_reduce_sum(s) * (1.f / CC);

    float vs = 0.f;
    for (int c = tid; c < CC; c += 256) { float d = buf[c] - mean; vs += d * d; }
    const float var  = block_reduce_sum(vs) * (1.f / CC);
    const float rstd = rsqrtf(var + LN_EPS);

    for (int c = tid; c < CC; c += 256) {
        out[(size_t)row * CC + c] =
            x[(size_t)row * CC + c] + (buf[c] - mean) * rstd * g[c] + b[c];
    }
}

// ---------------------------------------------------------------------------
// Launcher
// ---------------------------------------------------------------------------
extern "C" void kernel_launch(void* const* d_in, const int* in_sizes, int n_in,
                              void* d_out, int out_size)
{
    const float* x  = (const float*)d_in[0];
    const float* y  = (const float*)d_in[1];
    const float* Wq = (const float*)d_in[2];
    const float* Wk = (const float*)d_in[3];
    const float* Wv = (const float*)d_in[4];
    const float* Wm = (const float*)d_in[5];
    const float* W1 = (const float*)d_in[6];
    const float* W2 = (const float*)d_in[7];
    const float* g1 = (const float*)d_in[8];
    const float* b1 = (const float*)d_in[9];
    const float* g2 = (const float*)d_in[10];
    const float* b2 = (const float*)d_in[11];
    float* out = (float*)d_out;

    float *pQ, *pK, *pV, *pM1, *pM2;
    cudaGetSymbolAddress((void**)&pQ,  g_Q);
    cudaGetSymbolAddress((void**)&pK,  g_K);
    cudaGetSymbolAddress((void**)&pV,  g_V);
    cudaGetSymbolAddress((void**)&pM1, g_M1);
    cudaGetSymbolAddress((void**)&pM2, g_M2);

    __half *xh,*xl,*yh,*yl,*wqh,*wkh,*wvh,*wmh,*w1h,*w2h;
    __half *mh,*ml,*mlnh,*mlnl,*h1h,*h1l;
    cudaGetSymbolAddress((void**)&xh,  g_xh);  cudaGetSymbolAddress((void**)&xl,  g_xl);
    cudaGetSymbolAddress((void**)&yh,  g_yh);  cudaGetSymbolAddress((void**)&yl,  g_yl);
    cudaGetSymbolAddress((void**)&wqh, g_Wqh);
    cudaGetSymbolAddress((void**)&wkh, g_Wkh);
    cudaGetSymbolAddress((void**)&wvh, g_Wvh);
    cudaGetSymbolAddress((void**)&wmh, g_Wmh);
    cudaGetSymbolAddress((void**)&w1h, g_W1h);
    cudaGetSymbolAddress((void**)&w2h, g_W2h);
    cudaGetSymbolAddress((void**)&mh,  g_Mh);  cudaGetSymbolAddress((void**)&ml,  g_Ml);
    cudaGetSymbolAddress((void**)&mlnh,g_mlnh);cudaGetSymbolAddress((void**)&mlnl,g_mlnl);
    cudaGetSymbolAddress((void**)&h1h, g_H1h); cudaGetSymbolAddress((void**)&h1l, g_H1l);

    cudaFuncSetAttribute(hmma_gemm<0>, cudaFuncAttributeMaxDynamicSharedMemorySize, SMEM_GEMM);
    cudaFuncSetAttribute(hmma_gemm<1>, cudaFuncAttributeMaxDynamicSharedMemorySize, SMEM_GEMM);
    cudaFuncSetAttribute(hmma_gemm<2>, cudaFuncAttributeMaxDynamicSharedMemorySize, SMEM_GEMM);

    // ---- one mega split launch (weights: hi only)
    SplitJobs J;
    const float* srcs[NSPLIT] = {x, y, Wq, Wk, Wv, Wm, W1, W2};
    __half* his[NSPLIT] = {xh, yh, wqh, wkh, wvh, wmh, w1h, w2h};
    __half* los[NSPLIT] = {xl, yl, nullptr, nullptr, nullptr, nullptr, nullptr, nullptr};
    const int n4s[NSPLIT] = {NTOK * CC / 4, NTOK * CC / 4, CC * CC / 4, CC * CC / 4,
                             CC * CC / 4, CC * CC / 4, C2 * C2 / 4, CC * C2 / 4};
    int off = 0;
    for (int j = 0; j < NSPLIT; j++) {
        J.src[j] = srcs[j]; J.hi[j] = his[j]; J.lo[j] = los[j]; J.n4[j] = n4s[j];
        J.blkoff[j] = off;
        off += (n4s[j] + 255) / 256;
    }
    J.blkoff[NSPLIT] = off;
    split_all<<<off, 256>>>(J);

    const dim3 gP (CC / 128, NTOK / 128);
    const dim3 gW1(C2 / 128, NTOK / 128);
    const size_t sC = (size_t)CC * 2, sC2 = (size_t)C2 * 2;

    hmma_gemm<1><<<gP, 256, SMEM_GEMM>>>(xh, xl, xh, xl, wqh,
                                         pQ, nullptr, nullptr, CC, CC, 9999, sC, sC, 1.f);
    hmma_gemm<1><<<gP, 256, SMEM_GEMM>>>(yh, yl, yh, yl, wkh,
                                         pK, nullptr, nullptr, CC, CC, 9999, sC, sC, 1.f);
    hmma_gemm<0><<<gP, 256, SMEM_GEMM>>>(yh, yl, yh, yl, wvh,
                                         pV, nullptr, nullptr, CC, CC, 9999, sC, sC,
                                         1.f / (float)SEQS);

    zero_kv_kernel<<<(NB * NH * HD * HD + 255) / 256, 256>>>();
    kv_kernel<<<dim3(KV_SPLIT, NH, NB), 256>>>();
    msg_kernel<<<dim3(LL / 128, NH, NB), 128>>>();

    hmma_gemm<0><<<gP, 256, SMEM_GEMM>>>(mh, ml, mh, ml, wmh,
                                         pM1, nullptr, nullptr, CC, CC, 9999, sC, sC, 1.f);
    ln_split_kernel<<<NTOK, 256>>>(g1, b1);
    // W1: A = [x | LN(msg)] fused via dual source (chunks 0-7 from x, 8-15 from mln)
    hmma_gemm<2><<<gW1, 256, SMEM_GEMM>>>(xh, xl, mlnh, mlnl, w1h,
                                          nullptr, h1h, h1l, C2, C2, 8, sC, sC, 1.f);
    hmma_gemm<0><<<gP, 256, SMEM_GEMM>>>(h1h, h1l, h1h, h1l, w2h,
                                         pM2, nullptr, nullptr, CC, C2, 9999, sC2, sC2, 1.f);
    ln_add_kernel<<<NTOK, 256>>>(x, g2, b2, out);
}

// round 8
// speedup vs baseline: 1.4555x; 1.4555x over previous
#include <cuda_runtime.h>
#include <cuda_fp16.h>
#include <math.h>
#include <stdint.h>

// ---------------------------------------------------------------------------
// Problem constants
// ---------------------------------------------------------------------------
#define NB   4
#define LL   4096
#define SEQS 4096
#define CC   512
#define NH   8
#define HD   64
#define C2   1024
#define NTOK (NB * LL)          // 16384
#define EPS_Z 1e-6f
#define LN_EPS 1e-5f

// ---------------------------------------------------------------------------
// Scratch (device globals; no allocation allowed)
// ---------------------------------------------------------------------------
__device__ __align__(16) float g_Q [(size_t)NTOK * CC];
__device__ __align__(16) float g_K [(size_t)NTOK * CC];
__device__ __align__(16) float g_V [(size_t)NTOK * CC];
__device__ __align__(16) float g_KV[NB * NH * HD * HD];
__device__ __align__(16) float g_Ks[NB * NH * HD];
__device__ __align__(16) float g_M1[(size_t)NTOK * CC];
__device__ __align__(16) float g_M2[(size_t)NTOK * CC];

// split fp16 (hi/lo) activations; weights use hi only
__device__ __align__(16) __half g_xh[(size_t)NTOK * CC], g_xl[(size_t)NTOK * CC];
__device__ __align__(16) __half g_yh[(size_t)NTOK * CC], g_yl[(size_t)NTOK * CC];
__device__ __align__(16) __half g_Wqh[CC * CC];
__device__ __align__(16) __half g_Wkh[CC * CC];
__device__ __align__(16) __half g_Wvh[CC * CC];
__device__ __align__(16) __half g_Wmh[CC * CC];
__device__ __align__(16) __half g_W1h[C2 * C2];
__device__ __align__(16) __half g_W2h[CC * C2];
__device__ __align__(16) __half g_Mh  [(size_t)NTOK * CC], g_Ml [(size_t)NTOK * CC];
__device__ __align__(16) __half g_mlnh[(size_t)NTOK * CC];
__device__ __align__(16) __half g_H1h [(size_t)NTOK * C2];

// ---------------------------------------------------------------------------
// PTX helpers
// ---------------------------------------------------------------------------
__device__ __forceinline__ uint32_t smem_u32(const void* p)
{
    uint32_t a;
    asm("{ .reg .u64 t; cvta.to.shared.u64 t, %1; cvt.u32.u64 %0, t; }"
        : "=r"(a) : "l"(p));
    return a;
}

__device__ __forceinline__ void cpasync16(uint32_t dst, const void* src)
{
    asm volatile("cp.async.cg.shared.global [%0], [%1], 16;"
                 :: "r"(dst), "l"(src) : "memory");
}
__device__ __forceinline__ void cp_commit()
{
    asm volatile("cp.async.commit_group;" ::: "memory");
}
template <int N>
__device__ __forceinline__ void cp_wait()
{
    asm volatile("cp.async.wait_group %0;" :: "n"(N) : "memory");
}

__device__ __forceinline__ void ldm_x4(uint32_t& r0, uint32_t& r1,
                                       uint32_t& r2, uint32_t& r3, uint32_t a)
{
    asm volatile("ldmatrix.sync.aligned.m8n8.x4.shared.b16 {%0,%1,%2,%3}, [%4];"
                 : "=r"(r0), "=r"(r1), "=r"(r2), "=r"(r3) : "r"(a));
}

__device__ __forceinline__ void mma16816(float* c, const uint32_t* a,
                                         const uint32_t* b)
{
    asm volatile(
        "mma.sync.aligned.m16n8k16.row.col.f32.f16.f16.f32 "
        "{%0,%1,%2,%3}, {%4,%5,%6,%7}, {%8,%9}, {%0,%1,%2,%3};"
        : "+f"(c[0]), "+f"(c[1]), "+f"(c[2]), "+f"(c[3])
        : "r"(a[0]), "r"(a[1]), "r"(a[2]), "r"(a[3]), "r"(b[0]), "r"(b[1]));
}

// ---------------------------------------------------------------------------
// Mega split: fp32 -> fp16 hi/lo (lo null -> hi only)
// ---------------------------------------------------------------------------
#define NSPLIT 8
struct SplitJobs {
    const float* src[NSPLIT];
    __half* hi[NSPLIT];
    __half* lo[NSPLIT];
    int n4[NSPLIT];
    int blkoff[NSPLIT + 1];
};

__global__ void __launch_bounds__(256)
split_all(SplitJobs J)
{
    int b = blockIdx.x;
    int j = 0;
#pragma unroll
    for (int t = 0; t < NSPLIT - 1; t++)
        if (b >= J.blkoff[t + 1]) j = t + 1;
    const int i = (b - J.blkoff[j]) * 256 + threadIdx.x;
    if (i >= J.n4[j]) return;
    float4 v = ((const float4*)J.src[j])[i];
    __half h0 = __float2half_rn(v.x);
    __half h1 = __float2half_rn(v.y);
    __half h2 = __float2half_rn(v.z);
    __half h3 = __float2half_rn(v.w);
    ((__half2*)J.hi[j])[i * 2 + 0] = __half2(h0, h1);
    ((__half2*)J.hi[j])[i * 2 + 1] = __half2(h2, h3);
    if (J.lo[j]) {
        __half l0 = __float2half_rn(v.x - __half2float(h0));
        __half l1 = __float2half_rn(v.y - __half2float(h1));
        __half l2 = __float2half_rn(v.z - __half2float(h2));
        __half l3 = __float2half_rn(v.w - __half2float(h3));
        ((__half2*)J.lo[j])[i * 2 + 0] = __half2(l0, l1);
        ((__half2*)J.lo[j])[i * 2 + 1] = __half2(l2, l3);
    }
}

// ---------------------------------------------------------------------------
// fp16 HMMA GEMM. Tile 128x128, BK=32 fp32-K, 3-stage cp.async, 8 warps 2x4.
// NPASS=2: A split hi/lo (2 MMA passes). NPASS=1: A hi only.
// Dual A-source via kSplit (fused concat). EPI:
//   0 = scale -> f32 Cf
//   1 = elu+1 -> f32 Cf
//   2 = relu  -> fp16 Ch (hi only)
//   3 = fused KV: bx < gridDim.x/2 -> elu+1 -> Cf ; else -> *scale -> Cf2
// ---------------------------------------------------------------------------
#define ROWB   80
#define MATB   (128 * ROWB)       // 10240 B
#define STAGEB (3 * MATB)         // 30720 B (Ah, Al, Bh)
#define NSTG   3
#define SMEM_GEMM (NSTG * STAGEB) // 92160 B

template <int EPI, int NPASS>
__global__ void __launch_bounds__(256, 2)
hmma_gemm(const __half* __restrict__ A1h, const __half* __restrict__ A1l,
          const __half* __restrict__ A2h, const __half* __restrict__ A2l,
          const __half* __restrict__ Bh, const __half* __restrict__ B2h,
          float* __restrict__ Cf, float* __restrict__ Cf2,
          __half* __restrict__ Ch, int N, int K, int kSplit,
          size_t sA1b, size_t sA2b, float scale)
{
    extern __shared__ __align__(16) uint8_t dynsm[];
    const uint32_t sbase = smem_u32(dynsm);

    const int tid  = threadIdx.x;
    const int wid  = tid >> 5;
    const int lane = tid & 31;
    const int wr   = wid >> 2;
    const int wc   = wid & 3;
    const int bx   = blockIdx.x;
    const int by   = blockIdx.y;

    // fused-KV B select
    const int  halfx = (EPI == 3) ? ((int)gridDim.x >> 1) : 0;
    const bool isV   = (EPI == 3) && (bx >= halfx);
    const int  bn    = (EPI == 3) ? (isV ? bx - halfx : bx) : bx;
    const __half* Bsel = (EPI == 3 && isV) ? B2h : Bh;

    const int row0 = tid >> 2;               // 0..63
    const int cb   = (tid & 3) * 16;
    const size_t sBb = (size_t)K * 2;

    const char* gA1h = (const char*)A1h + (size_t)(by * 128 + row0) * sA1b + cb;
    const char* gA1l = (const char*)A1l + (size_t)(by * 128 + row0) * sA1b + cb;
    const char* gA2h = (const char*)A2h + (size_t)(by * 128 + row0) * sA2b + cb;
    const char* gA2l = (const char*)A2l + (size_t)(by * 128 + row0) * sA2b + cb;
    const char* gBh0 = (const char*)Bsel + (size_t)(bn * 128 + row0) * sBb + cb;
    const size_t rs1 = 64 * sA1b, rs2 = 64 * sA2b, rsB = 64 * sBb;

    const uint32_t dA0 = (uint32_t)(row0 * ROWB + cb);
    const uint32_t dA1 = (uint32_t)((row0 + 64) * ROWB + cb);

    auto issue = [&](int stage, int chunk) {
        const uint32_t s = sbase + stage * STAGEB;
        const char *ah, *al; size_t o, rs;
        if (chunk < kSplit) { ah = gA1h; al = gA1l; o = (size_t)chunk * 64; rs = rs1; }
        else { ah = gA2h; al = gA2l; o = (size_t)(chunk - kSplit) * 64; rs = rs2; }
        cpasync16(s + 0 * MATB + dA0, ah + o);
        cpasync16(s + 0 * MATB + dA1, ah + o + rs);
        if (NPASS == 2) {
            cpasync16(s + 1 * MATB + dA0, al + o);
            cpasync16(s + 1 * MATB + dA1, al + o + rs);
        }
        const size_t ob = (size_t)chunk * 64;
        cpasync16(s + 2 * MATB + dA0, gBh0 + ob);
        cpasync16(s + 2 * MATB + dA1, gBh0 + ob + rsB);
        cp_commit();
    };

    const uint32_t aRow = (uint32_t)(wr * 64 + (lane & 15));
    const uint32_t aCol = (uint32_t)((lane >> 4) << 4);
    const uint32_t bRow = (uint32_t)(wc * 32 + (lane & 7) + ((lane >> 4) << 3));
    const uint32_t bCol = (uint32_t)(((lane >> 3) & 1) << 4);

    float acc[4][4][4];
#pragma unroll
    for (int i = 0; i < 4; i++)
#pragma unroll
        for (int j = 0; j < 4; j++)
#pragma unroll
            for (int q = 0; q < 4; q++) acc[i][j][q] = 0.f;

    const int nch = K / 32;
    issue(0, 0);
    if (nch > 1) issue(1, 1);

    for (int c = 0; c < nch; c++) {
        if (c + 2 < nch) { issue((c + 2) % NSTG, c + 2); cp_wait<2>(); }
        else if (c + 1 < nch) { cp_wait<1>(); }
        else { cp_wait<0>(); }
        __syncthreads();

        const uint32_t s  = sbase + (c % NSTG) * STAGEB;
        const uint32_t pAh = s + 0 * MATB, pAl = s + 1 * MATB, pBh = s + 2 * MATB;

#pragma unroll
        for (int ks = 0; ks < 2; ks++) {
            const uint32_t kb = (uint32_t)(ks * 32);

            uint32_t ah[4][4], bh[2][4];
#pragma unroll
            for (int mi = 0; mi < 4; mi++)
                ldm_x4(ah[mi][0], ah[mi][1], ah[mi][2], ah[mi][3],
                       pAh + (aRow + mi * 16) * ROWB + kb + aCol);
#pragma unroll
            for (int ng = 0; ng < 2; ng++)
                ldm_x4(bh[ng][0], bh[ng][1], bh[ng][2], bh[ng][3],
                       pBh + (bRow + ng * 16) * ROWB + kb + bCol);
#pragma unroll
            for (int mi = 0; mi < 4; mi++)
#pragma unroll
                for (int ni = 0; ni < 4; ni++)
                    mma16816(acc[mi][ni], ah[mi], &bh[ni >> 1][(ni & 1) * 2]);

            if (NPASS == 2) {
#pragma unroll
                for (int mi = 0; mi < 4; mi++) {
                    uint32_t al[4];
                    ldm_x4(al[0], al[1], al[2], al[3],
                           pAl + (aRow + mi * 16) * ROWB + kb + aCol);
#pragma unroll
                    for (int ni = 0; ni < 4; ni++)
                        mma16816(acc[mi][ni], al, &bh[ni >> 1][(ni & 1) * 2]);
                }
            }
        }
        __syncthreads();
    }

    // ---- epilogue
#pragma unroll
    for (int mi = 0; mi < 4; mi++) {
#pragma unroll
        for (int ni = 0; ni < 4; ni++) {
            const int r = by * 128 + wr * 64 + mi * 16 + (lane >> 2);
            const int cn = bn * 128 + wc * 32 + ni * 8 + (lane & 3) * 2;
            float v0 = acc[mi][ni][0];
            float v1 = acc[mi][ni][1];
            float v2 = acc[mi][ni][2];
            float v3 = acc[mi][ni][3];
            if (EPI == 0) { v0 *= scale; v1 *= scale; v2 *= scale; v3 *= scale; }
            if (EPI == 1 || (EPI == 3 && !isV)) {
                v0 = (v0 > 0.f) ? (v0 + 1.f) : expf(v0);
                v1 = (v1 > 0.f) ? (v1 + 1.f) : expf(v1);
                v2 = (v2 > 0.f) ? (v2 + 1.f) : expf(v2);
                v3 = (v3 > 0.f) ? (v3 + 1.f) : expf(v3);
            }
            if (EPI == 3 && isV) { v0 *= scale; v1 *= scale; v2 *= scale; v3 *= scale; }

            if (EPI == 2) {
                v0 = fmaxf(v0, 0.f); v1 = fmaxf(v1, 0.f);
                v2 = fmaxf(v2, 0.f); v3 = fmaxf(v3, 0.f);
                *(__half2*)(Ch + (size_t)r * N + cn) =
                    __half2(__float2half_rn(v0), __float2half_rn(v1));
                *(__half2*)(Ch + (size_t)(r + 8) * N + cn) =
                    __half2(__float2half_rn(v2), __float2half_rn(v3));
            } else {
                float* outp = (EPI == 3 && isV) ? Cf2 : Cf;
                *(float2*)(outp + (size_t)r * N + cn) = make_float2(v0, v1);
                *(float2*)(outp + (size_t)(r + 8) * N + cn) = make_float2(v2, v3);
            }
        }
    }
}

// ---------------------------------------------------------------------------
// Zero KV / Ksum accumulators
// ---------------------------------------------------------------------------
__global__ void zero_kv_kernel()
{
    int i = blockIdx.x * blockDim.x + threadIdx.x;
    if (i < NB * NH * HD * HD) g_KV[i] = 0.f;
    if (i < NB * NH * HD)      g_Ks[i] = 0.f;
}

// ---------------------------------------------------------------------------
// KV[n,h,d,v] = sum_s K[n,s,h,d]*V[n,s,h,v] ; Ksum[n,h,d] = sum_s K[n,s,h,d]
// ---------------------------------------------------------------------------
#define KV_SPLIT 16
__global__ void __launch_bounds__(256)
kv_kernel()
{
    const int n = blockIdx.z, h = blockIdx.y, sp = blockIdx.x;
    const int SPS = SEQS / KV_SPLIT;
    const int s0  = sp * SPS;

    __shared__ float Ksm[16][HD];
    __shared__ float Vsm[16][HD];

    const int tid = threadIdx.x;
    const int d0  = (tid >> 4) * 4;
    const int v0  = (tid & 15) * 4;
    const int lr  = tid >> 4;
    const int lq  = (tid & 15) * 4;

    float acc[4][4];
#pragma unroll
    for (int i = 0; i < 4; i++)
#pragma unroll
        for (int j = 0; j < 4; j++) acc[i][j] = 0.f;
    float ksacc[4] = {0.f, 0.f, 0.f, 0.f};

    for (int sc = 0; sc < SPS; sc += 16) {
        const size_t base = ((size_t)(n * SEQS + s0 + sc + lr)) * CC + h * HD + lq;
        float4 kv4 = *(const float4*)(g_K + base);
        Ksm[lr][lq + 0] = kv4.x; Ksm[lr][lq + 1] = kv4.y;
        Ksm[lr][lq + 2] = kv4.z; Ksm[lr][lq + 3] = kv4.w;
        float4 vv4 = *(const float4*)(g_V + base);
        Vsm[lr][lq + 0] = vv4.x; Vsm[lr][lq + 1] = vv4.y;
        Vsm[lr][lq + 2] = vv4.z; Vsm[lr][lq + 3] = vv4.w;
        __syncthreads();

#pragma unroll
        for (int s = 0; s < 16; s++) {
            float a[4], b[4];
#pragma unroll
            for (int i = 0; i < 4; i++) a[i] = Ksm[s][d0 + i];
#pragma unroll
            for (int j = 0; j < 4; j++) b[j] = Vsm[s][v0 + j];
#pragma unroll
            for (int i = 0; i < 4; i++)
#pragma unroll
                for (int j = 0; j < 4; j++) acc[i][j] = fmaf(a[i], b[j], acc[i][j]);
            if (v0 == 0) {
#pragma unroll
                for (int i = 0; i < 4; i++) ksacc[i] += a[i];
            }
        }
        __syncthreads();
    }

    float* KVp = g_KV + (size_t)(n * NH + h) * HD * HD;
#pragma unroll
    for (int i = 0; i < 4; i++)
#pragma unroll
        for (int j = 0; j < 4; j++)
            atomicAdd(&KVp[(d0 + i) * HD + v0 + j], acc[i][j]);
    if (v0 == 0) {
        float* Kp = g_Ks + (n * NH + h) * HD;
#pragma unroll
        for (int i = 0; i < 4; i++) atomicAdd(&Kp[d0 + i], ksacc[i]);
    }
}

// ---------------------------------------------------------------------------
// message: one thread per l-row, KV broadcast from smem, no inner syncs.
// ---------------------------------------------------------------------------
__global__ void __launch_bounds__(128)
msg_kernel()
{
    const int n = blockIdx.z, h = blockIdx.y, lt = blockIdx.x;
    __shared__ float KVs[HD][HD];
    __shared__ float Kss[HD];

    const int tid = threadIdx.x;
    const size_t kvbase = (size_t)(n * NH + h) * HD * HD;
    for (int idx = tid; idx < HD * HD; idx += 128)
        KVs[idx >> 6][idx & 63] = g_KV[kvbase + idx];
    if (tid < HD) Kss[tid] = g_Ks[(n * NH + h) * HD + tid];
    __syncthreads();

    const int l = lt * 128 + tid;
    const size_t qbase = ((size_t)(n * LL + l)) * CC + h * HD;

    float acc[HD];
#pragma unroll
    for (int v = 0; v < HD; v++) acc[v] = 0.f;
    float zden = EPS_Z;

#pragma unroll
    for (int d0 = 0; d0 < HD; d0 += 4) {
        const float4 q4 = *(const float4*)(g_Q + qbase + d0);
        const float qv[4] = {q4.x, q4.y, q4.z, q4.w};
#pragma unroll
        for (int dd = 0; dd < 4; dd++) {
            const float q = qv[dd];
            zden = fmaf(q, Kss[d0 + dd], zden);
#pragma unroll
            for (int v0 = 0; v0 < HD; v0 += 4) {
                const float4 kv = *(const float4*)&KVs[d0 + dd][v0];
                acc[v0 + 0] = fmaf(q, kv.x, acc[v0 + 0]);
                acc[v0 + 1] = fmaf(q, kv.y, acc[v0 + 1]);
                acc[v0 + 2] = fmaf(q, kv.z, acc[v0 + 2]);
                acc[v0 + 3] = fmaf(q, kv.w, acc[v0 + 3]);
            }
        }
    }

    const float zs = (float)SEQS / zden;
#pragma unroll
    for (int v = 0; v < HD; v += 2) {
        const float r0 = acc[v] * zs, r1 = acc[v + 1] * zs;
        const __half h0 = __float2half_rn(r0);
        const __half h1 = __float2half_rn(r1);
        *(__half2*)(g_Mh + qbase + v) = __half2(h0, h1);
        *(__half2*)(g_Ml + qbase + v) =
            __half2(__float2half_rn(r0 - __half2float(h0)),
                    __float2half_rn(r1 - __half2float(h1)));
    }
}

// ---------------------------------------------------------------------------
// Block reduction helper (256 threads)
// ---------------------------------------------------------------------------
__device__ __forceinline__ float block_reduce_sum(float v)
{
    __shared__ float red[8];
    const int lane = threadIdx.x & 31, w = threadIdx.x >> 5;
#pragma unroll
    for (int o = 16; o; o >>= 1) v += __shfl_down_sync(0xffffffffu, v, o);
    if (lane == 0) red[w] = v;
    __syncthreads();
    float t = (threadIdx.x < 8) ? red[threadIdx.x] : 0.f;
    if (w == 0) {
#pragma unroll
        for (int o = 4; o; o >>= 1) t += __shfl_down_sync(0xffu, t, o);
        if (lane == 0) red[0] = t;
    }
    __syncthreads();
    float r = red[0];
    __syncthreads();
    return r;
}

// ---------------------------------------------------------------------------
// LN(M1) -> fp16 hi (message half of the concat; W1 is 1-pass so no lo).
// ---------------------------------------------------------------------------
__global__ void __launch_bounds__(256)
ln_split_kernel(const float* __restrict__ g, const float* __restrict__ b)
{
    const int row = blockIdx.x;
    __shared__ float buf[CC];
    const float* mr = g_M1 + (size_t)row * CC;
    const int tid = threadIdx.x;

    float s = 0.f;
    for (int c = tid; c < CC; c += 256) { float v = mr[c]; buf[c] = v; s += v; }
    const float mean = block_reduce_sum(s) * (1.f / CC);

    float vs = 0.f;
    for (int c = tid; c < CC; c += 256) { float d = buf[c] - mean; vs += d * d; }
    const float var  = block_reduce_sum(vs) * (1.f / CC);
    const float rstd = rsqrtf(var + LN_EPS);

    for (int c = tid; c < CC; c += 256) {
        const float lv = (buf[c] - mean) * rstd * g[c] + b[c];
        g_mlnh[(size_t)row * CC + c] = __float2half_rn(lv);
    }
}

// ---------------------------------------------------------------------------
// out = x + LN(M2). One block per row.
// ---------------------------------------------------------------------------
__global__ void __launch_bounds__(256)
ln_add_kernel(const float* __restrict__ x,
              const float* __restrict__ g, const float* __restrict__ b,
              float* __restrict__ out)
{
    const int row = blockIdx.x;
    __shared__ float buf[CC];
    const float* mr = g_M2 + (size_t)row * CC;
    const int tid = threadIdx.x;

    float s = 0.f;
    for (int c = tid; c < CC; c += 256) { float v = mr[c]; buf[c] = v; s += v; }
    const float mean = block_reduce_sum(s) * (1.f / CC);

    float vs = 0.f;
    for (int c = tid; c < CC; c += 256) { float d = buf[c] - mean; vs += d * d; }
    const float var  = block_reduce_sum(vs) * (1.f / CC);
    const float rstd = rsqrtf(var + LN_EPS);

    for (int c = tid; c < CC; c += 256) {
        out[(size_t)row * CC + c] =
            x[(size_t)row * CC + c] + (buf[c] - mean) * rstd * g[c] + b[c];
    }
}

// ---------------------------------------------------------------------------
// Launcher
// ---------------------------------------------------------------------------
extern "C" void kernel_launch(void* const* d_in, const int* in_sizes, int n_in,
                              void* d_out, int out_size)
{
    const float* x  = (const float*)d_in[0];
    const float* y  = (const float*)d_in[1];
    const float* Wq = (const float*)d_in[2];
    const float* Wk = (const float*)d_in[3];
    const float* Wv = (const float*)d_in[4];
    const float* Wm = (const float*)d_in[5];
    const float* W1 = (const float*)d_in[6];
    const float* W2 = (const float*)d_in[7];
    const float* g1 = (const float*)d_in[8];
    const float* b1 = (const float*)d_in[9];
    const float* g2 = (const float*)d_in[10];
    const float* b2 = (const float*)d_in[11];
    float* out = (float*)d_out;

    float *pQ, *pK, *pV, *pM1, *pM2;
    cudaGetSymbolAddress((void**)&pQ,  g_Q);
    cudaGetSymbolAddress((void**)&pK,  g_K);
    cudaGetSymbolAddress((void**)&pV,  g_V);
    cudaGetSymbolAddress((void**)&pM1, g_M1);
    cudaGetSymbolAddress((void**)&pM2, g_M2);

    __half *xh,*xl,*yh,*yl,*wqh,*wkh,*wvh,*wmh,*w1h,*w2h;
    __half *mh,*ml,*mlnh,*h1h;
    cudaGetSymbolAddress((void**)&xh,  g_xh);  cudaGetSymbolAddress((void**)&xl,  g_xl);
    cudaGetSymbolAddress((void**)&yh,  g_yh);  cudaGetSymbolAddress((void**)&yl,  g_yl);
    cudaGetSymbolAddress((void**)&wqh, g_Wqh);
    cudaGetSymbolAddress((void**)&wkh, g_Wkh);
    cudaGetSymbolAddress((void**)&wvh, g_Wvh);
    cudaGetSymbolAddress((void**)&wmh, g_Wmh);
    cudaGetSymbolAddress((void**)&w1h, g_W1h);
    cudaGetSymbolAddress((void**)&w2h, g_W2h);
    cudaGetSymbolAddress((void**)&mh,  g_Mh);  cudaGetSymbolAddress((void**)&ml,  g_Ml);
    cudaGetSymbolAddress((void**)&mlnh,g_mlnh);
    cudaGetSymbolAddress((void**)&h1h, g_H1h);

    cudaFuncSetAttribute(hmma_gemm<0,2>, cudaFuncAttributeMaxDynamicSharedMemorySize, SMEM_GEMM);
    cudaFuncSetAttribute(hmma_gemm<1,2>, cudaFuncAttributeMaxDynamicSharedMemorySize, SMEM_GEMM);
    cudaFuncSetAttribute(hmma_gemm<3,2>, cudaFuncAttributeMaxDynamicSharedMemorySize, SMEM_GEMM);
    cudaFuncSetAttribute(hmma_gemm<2,1>, cudaFuncAttributeMaxDynamicSharedMemorySize, SMEM_GEMM);
    cudaFuncSetAttribute(hmma_gemm<0,1>, cudaFuncAttributeMaxDynamicSharedMemorySize, SMEM_GEMM);

    // ---- one mega split launch (weights: hi only)
    SplitJobs J;
    const float* srcs[NSPLIT] = {x, y, Wq, Wk, Wv, Wm, W1, W2};
    __half* his[NSPLIT] = {xh, yh, wqh, wkh, wvh, wmh, w1h, w2h};
    __half* los[NSPLIT] = {xl, yl, nullptr, nullptr, nullptr, nullptr, nullptr, nullptr};
    const int n4s[NSPLIT] = {NTOK * CC / 4, NTOK * CC / 4, CC * CC / 4, CC * CC / 4,
                             CC * CC / 4, CC * CC / 4, C2 * C2 / 4, CC * C2 / 4};
    int off = 0;
    for (int j = 0; j < NSPLIT; j++) {
        J.src[j] = srcs[j]; J.hi[j] = his[j]; J.lo[j] = los[j]; J.n4[j] = n4s[j];
        J.blkoff[j] = off;
        off += (n4s[j] + 255) / 256;
    }
    J.blkoff[NSPLIT] = off;
    split_all<<<off, 256>>>(J);

    const dim3 gP  (CC / 128, NTOK / 128);      // 4 x 128
    const dim3 gKV (2 * CC / 128, NTOK / 128);  // 8 x 128 (K then V)
    const dim3 gW1 (C2 / 128, NTOK / 128);      // 8 x 128
    const size_t sC = (size_t)CC * 2, sC2 = (size_t)C2 * 2;

    // Q projection (2-pass, elu+1)
    hmma_gemm<1,2><<<gP, 256, SMEM_GEMM>>>(xh, xl, xh, xl, wqh, nullptr,
                                           pQ, nullptr, nullptr, CC, CC, 9999, sC, sC, 1.f);
    // K+V fused (2-pass): bx<4 -> K=elu(y@Wk)+1, bx>=4 -> V=(y@Wv)/S
    hmma_gemm<3,2><<<gKV, 256, SMEM_GEMM>>>(yh, yl, yh, yl, wkh, wvh,
                                            pK, pV, nullptr, CC, CC, 9999, sC, sC,
                                            1.f / (float)SEQS);

    zero_kv_kernel<<<(NB * NH * HD * HD + 255) / 256, 256>>>();
    kv_kernel<<<dim3(KV_SPLIT, NH, NB), 256>>>();
    msg_kernel<<<dim3(LL / 128, NH, NB), 128>>>();

    // Wm (2-pass)
    hmma_gemm<0,2><<<gP, 256, SMEM_GEMM>>>(mh, ml, mh, ml, wmh, nullptr,
                                           pM1, nullptr, nullptr, CC, CC, 9999, sC, sC, 1.f);
    ln_split_kernel<<<NTOK, 256>>>(g1, b1);
    // W1 (1-pass, relu -> fp16 hi): A = [x | LN(msg)] dual source
    hmma_gemm<2,1><<<gW1, 256, SMEM_GEMM>>>(xh, xh, mlnh, mlnh, w1h, nullptr,
                                            nullptr, nullptr, h1h, C2, C2, 16, sC, sC, 1.f);
    // W2 (1-pass)
    hmma_gemm<0,1><<<gP, 256, SMEM_GEMM>>>(h1h, h1h, h1h, h1h, w2h, nullptr,
                                           pM2, nullptr, nullptr, CC, C2, 9999, sC2, sC2, 1.f);
    ln_add_kernel<<<NTOK, 256>>>(x, g2, b2, out);
}

// round 9
// speedup vs baseline: 1.6303x; 1.1200x over previous
#include <cuda_runtime.h>
#include <cuda_fp16.h>
#include <math.h>
#include <stdint.h>

// ---------------------------------------------------------------------------
// Problem constants
// ---------------------------------------------------------------------------
#define NB   4
#define LL   4096
#define SEQS 4096
#define CC   512
#define NH   8
#define HD   64
#define C2   1024
#define NTOK (NB * LL)          // 16384
#define EPS_Z 1e-6f
#define LN_EPS 1e-5f

// ---------------------------------------------------------------------------
// Scratch (device globals; no allocation allowed)
// ---------------------------------------------------------------------------
__device__ __align__(16) float g_Q [(size_t)NTOK * CC];
__device__ __align__(16) float g_K [(size_t)NTOK * CC];
__device__ __align__(16) float g_V [(size_t)NTOK * CC];
__device__ __align__(16) float g_KV[NB * NH * HD * HD];
__device__ __align__(16) float g_Ks[NB * NH * HD];
__device__ __align__(16) float g_M1[(size_t)NTOK * CC];
__device__ __align__(16) float g_M2[(size_t)NTOK * CC];

// fp16 buffers (hi everywhere; lo only for message -> Wm 2-pass)
__device__ __align__(16) __half g_xh[(size_t)NTOK * CC];
__device__ __align__(16) __half g_yh[(size_t)NTOK * CC];
__device__ __align__(16) __half g_Wqh[CC * CC];
__device__ __align__(16) __half g_Wkh[CC * CC];
__device__ __align__(16) __half g_Wvh[CC * CC];
__device__ __align__(16) __half g_Wmh[CC * CC];
__device__ __align__(16) __half g_W1h[C2 * C2];
__device__ __align__(16) __half g_W2h[CC * C2];
__device__ __align__(16) __half g_Mh  [(size_t)NTOK * CC], g_Ml [(size_t)NTOK * CC];
__device__ __align__(16) __half g_mlnh[(size_t)NTOK * CC];
__device__ __align__(16) __half g_H1h [(size_t)NTOK * C2];

// ---------------------------------------------------------------------------
// PTX helpers
// ---------------------------------------------------------------------------
__device__ __forceinline__ uint32_t smem_u32(const void* p)
{
    uint32_t a;
    asm("{ .reg .u64 t; cvta.to.shared.u64 t, %1; cvt.u32.u64 %0, t; }"
        : "=r"(a) : "l"(p));
    return a;
}

__device__ __forceinline__ void cpasync16(uint32_t dst, const void* src)
{
    asm volatile("cp.async.cg.shared.global [%0], [%1], 16;"
                 :: "r"(dst), "l"(src) : "memory");
}
__device__ __forceinline__ void cp_commit()
{
    asm volatile("cp.async.commit_group;" ::: "memory");
}
template <int N>
__device__ __forceinline__ void cp_wait()
{
    asm volatile("cp.async.wait_group %0;" :: "n"(N) : "memory");
}

__device__ __forceinline__ void ldm_x4(uint32_t& r0, uint32_t& r1,
                                       uint32_t& r2, uint32_t& r3, uint32_t a)
{
    asm volatile("ldmatrix.sync.aligned.m8n8.x4.shared.b16 {%0,%1,%2,%3}, [%4];"
                 : "=r"(r0), "=r"(r1), "=r"(r2), "=r"(r3) : "r"(a));
}

__device__ __forceinline__ void mma16816(float* c, const uint32_t* a,
                                         const uint32_t* b)
{
    asm volatile(
        "mma.sync.aligned.m16n8k16.row.col.f32.f16.f16.f32 "
        "{%0,%1,%2,%3}, {%4,%5,%6,%7}, {%8,%9}, {%0,%1,%2,%3};"
        : "+f"(c[0]), "+f"(c[1]), "+f"(c[2]), "+f"(c[3])
        : "r"(a[0]), "r"(a[1]), "r"(a[2]), "r"(a[3]), "r"(b[0]), "r"(b[1]));
}

// ---------------------------------------------------------------------------
// Mega split: fp32 -> fp16 (hi only)
// ---------------------------------------------------------------------------
#define NSPLIT 8
struct SplitJobs {
    const float* src[NSPLIT];
    __half* hi[NSPLIT];
    int n4[NSPLIT];
    int blkoff[NSPLIT + 1];
};

__global__ void __launch_bounds__(256)
split_all(SplitJobs J)
{
    int b = blockIdx.x;
    int j = 0;
#pragma unroll
    for (int t = 0; t < NSPLIT - 1; t++)
        if (b >= J.blkoff[t + 1]) j = t + 1;
    const int i = (b - J.blkoff[j]) * 256 + threadIdx.x;
    if (i >= J.n4[j]) return;
    float4 v = ((const float4*)J.src[j])[i];
    ((__half2*)J.hi[j])[i * 2 + 0] =
        __half2(__float2half_rn(v.x), __float2half_rn(v.y));
    ((__half2*)J.hi[j])[i * 2 + 1] =
        __half2(__float2half_rn(v.z), __float2half_rn(v.w));
}

// ---------------------------------------------------------------------------
// fp16 HMMA GEMM. Tile 128x128, BK=32 fp32-K, 3-stage cp.async, 8 warps 2x4.
// NPASS=2: A split hi/lo. NPASS=1: A hi only.
// Dual A-source via kSplit (fused concat). EPI:
//   0 = scale -> f32 Cf
//   1 = elu+1 -> f32 Cf
//   2 = relu  -> fp16 Ch (hi only)
//   3 = fused KV: bx < gridDim.x/2 -> elu+1 -> Cf ; else -> *scale -> Cf2
// ---------------------------------------------------------------------------
#define ROWB   80
#define MATB   (128 * ROWB)       // 10240 B
#define STAGEB (3 * MATB)         // 30720 B (Ah, Al, Bh)
#define NSTG   3
#define SMEM_GEMM (NSTG * STAGEB) // 92160 B

template <int EPI, int NPASS>
__global__ void __launch_bounds__(256, 2)
hmma_gemm(const __half* __restrict__ A1h, const __half* __restrict__ A1l,
          const __half* __restrict__ A2h, const __half* __restrict__ A2l,
          const __half* __restrict__ Bh, const __half* __restrict__ B2h,
          float* __restrict__ Cf, float* __restrict__ Cf2,
          __half* __restrict__ Ch, int N, int K, int kSplit,
          size_t sA1b, size_t sA2b, float scale)
{
    extern __shared__ __align__(16) uint8_t dynsm[];
    const uint32_t sbase = smem_u32(dynsm);

    const int tid  = threadIdx.x;
    const int wid  = tid >> 5;
    const int lane = tid & 31;
    const int wr   = wid >> 2;
    const int wc   = wid & 3;
    const int bx   = blockIdx.x;
    const int by   = blockIdx.y;

    // fused-KV B select
    const int  halfx = (EPI == 3) ? ((int)gridDim.x >> 1) : 0;
    const bool isV   = (EPI == 3) && (bx >= halfx);
    const int  bn    = (EPI == 3) ? (isV ? bx - halfx : bx) : bx;
    const __half* Bsel = (EPI == 3 && isV) ? B2h : Bh;

    const int row0 = tid >> 2;               // 0..63
    const int cb   = (tid & 3) * 16;
    const size_t sBb = (size_t)K * 2;

    const char* gA1h = (const char*)A1h + (size_t)(by * 128 + row0) * sA1b + cb;
    const char* gA1l = (const char*)A1l + (size_t)(by * 128 + row0) * sA1b + cb;
    const char* gA2h = (const char*)A2h + (size_t)(by * 128 + row0) * sA2b + cb;
    const char* gA2l = (const char*)A2l + (size_t)(by * 128 + row0) * sA2b + cb;
    const char* gBh0 = (const char*)Bsel + (size_t)(bn * 128 + row0) * sBb + cb;
    const size_t rs1 = 64 * sA1b, rs2 = 64 * sA2b, rsB = 64 * sBb;

    const uint32_t dA0 = (uint32_t)(row0 * ROWB + cb);
    const uint32_t dA1 = (uint32_t)((row0 + 64) * ROWB + cb);

    auto issue = [&](int stage, int chunk) {
        const uint32_t s = sbase + stage * STAGEB;
        const char *ah, *al; size_t o, rs;
        if (chunk < kSplit) { ah = gA1h; al = gA1l; o = (size_t)chunk * 64; rs = rs1; }
        else { ah = gA2h; al = gA2l; o = (size_t)(chunk - kSplit) * 64; rs = rs2; }
        cpasync16(s + 0 * MATB + dA0, ah + o);
        cpasync16(s + 0 * MATB + dA1, ah + o + rs);
        if (NPASS == 2) {
            cpasync16(s + 1 * MATB + dA0, al + o);
            cpasync16(s + 1 * MATB + dA1, al + o + rs);
        }
        const size_t ob = (size_t)chunk * 64;
        cpasync16(s + 2 * MATB + dA0, gBh0 + ob);
        cpasync16(s + 2 * MATB + dA1, gBh0 + ob + rsB);
        cp_commit();
    };

    const uint32_t aRow = (uint32_t)(wr * 64 + (lane & 15));
    const uint32_t aCol = (uint32_t)((lane >> 4) << 4);
    const uint32_t bRow = (uint32_t)(wc * 32 + (lane & 7) + ((lane >> 4) << 3));
    const uint32_t bCol = (uint32_t)(((lane >> 3) & 1) << 4);

    float acc[4][4][4];
#pragma unroll
    for (int i = 0; i < 4; i++)
#pragma unroll
        for (int j = 0; j < 4; j++)
#pragma unroll
            for (int q = 0; q < 4; q++) acc[i][j][q] = 0.f;

    const int nch = K / 32;
    issue(0, 0);
    if (nch > 1) issue(1, 1);

    for (int c = 0; c < nch; c++) {
        if (c + 2 < nch) { issue((c + 2) % NSTG, c + 2); cp_wait<2>(); }
        else if (c + 1 < nch) { cp_wait<1>(); }
        else { cp_wait<0>(); }
        __syncthreads();

        const uint32_t s  = sbase + (c % NSTG) * STAGEB;
        const uint32_t pAh = s + 0 * MATB, pAl = s + 1 * MATB, pBh = s + 2 * MATB;

#pragma unroll
        for (int ks = 0; ks < 2; ks++) {
            const uint32_t kb = (uint32_t)(ks * 32);

            uint32_t ah[4][4], bh[2][4];
#pragma unroll
            for (int mi = 0; mi < 4; mi++)
                ldm_x4(ah[mi][0], ah[mi][1], ah[mi][2], ah[mi][3],
                       pAh + (aRow + mi * 16) * ROWB + kb + aCol);
#pragma unroll
            for (int ng = 0; ng < 2; ng++)
                ldm_x4(bh[ng][0], bh[ng][1], bh[ng][2], bh[ng][3],
                       pBh + (bRow + ng * 16) * ROWB + kb + bCol);
#pragma unroll
            for (int mi = 0; mi < 4; mi++)
#pragma unroll
                for (int ni = 0; ni < 4; ni++)
                    mma16816(acc[mi][ni], ah[mi], &bh[ni >> 1][(ni & 1) * 2]);

            if (NPASS == 2) {
#pragma unroll
                for (int mi = 0; mi < 4; mi++) {
                    uint32_t al[4];
                    ldm_x4(al[0], al[1], al[2], al[3],
                           pAl + (aRow + mi * 16) * ROWB + kb + aCol);
#pragma unroll
                    for (int ni = 0; ni < 4; ni++)
                        mma16816(acc[mi][ni], al, &bh[ni >> 1][(ni & 1) * 2]);
                }
            }
        }
        __syncthreads();
    }

    // ---- epilogue
#pragma unroll
    for (int mi = 0; mi < 4; mi++) {
#pragma unroll
        for (int ni = 0; ni < 4; ni++) {
            const int r = by * 128 + wr * 64 + mi * 16 + (lane >> 2);
            const int cn = bn * 128 + wc * 32 + ni * 8 + (lane & 3) * 2;
            float v0 = acc[mi][ni][0];
            float v1 = acc[mi][ni][1];
            float v2 = acc[mi][ni][2];
            float v3 = acc[mi][ni][3];
            if (EPI == 0) { v0 *= scale; v1 *= scale; v2 *= scale; v3 *= scale; }
            if (EPI == 1 || (EPI == 3 && !isV)) {
                v0 = (v0 > 0.f) ? (v0 + 1.f) : expf(v0);
                v1 = (v1 > 0.f) ? (v1 + 1.f) : expf(v1);
                v2 = (v2 > 0.f) ? (v2 + 1.f) : expf(v2);
                v3 = (v3 > 0.f) ? (v3 + 1.f) : expf(v3);
            }
            if (EPI == 3 && isV) { v0 *= scale; v1 *= scale; v2 *= scale; v3 *= scale; }

            if (EPI == 2) {
                v0 = fmaxf(v0, 0.f); v1 = fmaxf(v1, 0.f);
                v2 = fmaxf(v2, 0.f); v3 = fmaxf(v3, 0.f);
                *(__half2*)(Ch + (size_t)r * N + cn) =
                    __half2(__float2half_rn(v0), __float2half_rn(v1));
                *(__half2*)(Ch + (size_t)(r + 8) * N + cn) =
                    __half2(__float2half_rn(v2), __float2half_rn(v3));
            } else {
                float* outp = (EPI == 3 && isV) ? Cf2 : Cf;
                *(float2*)(outp + (size_t)r * N + cn) = make_float2(v0, v1);
                *(float2*)(outp + (size_t)(r + 8) * N + cn) = make_float2(v2, v3);
            }
        }
    }
}

// ---------------------------------------------------------------------------
// Zero KV / Ksum accumulators
// ---------------------------------------------------------------------------
__global__ void zero_kv_kernel()
{
    int i = blockIdx.x * blockDim.x + threadIdx.x;
    if (i < NB * NH * HD * HD) g_KV[i] = 0.f;
    if (i < NB * NH * HD)      g_Ks[i] = 0.f;
}

// ---------------------------------------------------------------------------
// KV[n,h,d,v] = sum_s K[n,s,h,d]*V[n,s,h,v] ; Ksum[n,h,d] = sum_s K[n,s,h,d]
// ---------------------------------------------------------------------------
#define KV_SPLIT 16
__global__ void __launch_bounds__(256)
kv_kernel()
{
    const int n = blockIdx.z, h = blockIdx.y, sp = blockIdx.x;
    const int SPS = SEQS / KV_SPLIT;
    const int s0  = sp * SPS;

    __shared__ float Ksm[16][HD];
    __shared__ float Vsm[16][HD];

    const int tid = threadIdx.x;
    const int d0  = (tid >> 4) * 4;
    const int v0  = (tid & 15) * 4;
    const int lr  = tid >> 4;
    const int lq  = (tid & 15) * 4;

    float acc[4][4];
#pragma unroll
    for (int i = 0; i < 4; i++)
#pragma unroll
        for (int j = 0; j < 4; j++) acc[i][j] = 0.f;
    float ksacc[4] = {0.f, 0.f, 0.f, 0.f};

    for (int sc = 0; sc < SPS; sc += 16) {
        const size_t base = ((size_t)(n * SEQS + s0 + sc + lr)) * CC + h * HD + lq;
        float4 kv4 = *(const float4*)(g_K + base);
        Ksm[lr][lq + 0] = kv4.x; Ksm[lr][lq + 1] = kv4.y;
        Ksm[lr][lq + 2] = kv4.z; Ksm[lr][lq + 3] = kv4.w;
        float4 vv4 = *(const float4*)(g_V + base);
        Vsm[lr][lq + 0] = vv4.x; Vsm[lr][lq + 1] = vv4.y;
        Vsm[lr][lq + 2] = vv4.z; Vsm[lr][lq + 3] = vv4.w;
        __syncthreads();

#pragma unroll
        for (int s = 0; s < 16; s++) {
            float a[4], b[4];
#pragma unroll
            for (int i = 0; i < 4; i++) a[i] = Ksm[s][d0 + i];
#pragma unroll
            for (int j = 0; j < 4; j++) b[j] = Vsm[s][v0 + j];
#pragma unroll
            for (int i = 0; i < 4; i++)
#pragma unroll
                for (int j = 0; j < 4; j++) acc[i][j] = fmaf(a[i], b[j], acc[i][j]);
            if (v0 == 0) {
#pragma unroll
                for (int i = 0; i < 4; i++) ksacc[i] += a[i];
            }
        }
        __syncthreads();
    }

    float* KVp = g_KV + (size_t)(n * NH + h) * HD * HD;
#pragma unroll
    for (int i = 0; i < 4; i++)
#pragma unroll
        for (int j = 0; j < 4; j++)
            atomicAdd(&KVp[(d0 + i) * HD + v0 + j], acc[i][j]);
    if (v0 == 0) {
        float* Kp = g_Ks + (n * NH + h) * HD;
#pragma unroll
        for (int i = 0; i < 4; i++) atomicAdd(&Kp[d0 + i], ksacc[i]);
    }
}

// ---------------------------------------------------------------------------
// message: one thread per l-row, KV broadcast from smem, no inner syncs.
// ---------------------------------------------------------------------------
__global__ void __launch_bounds__(128)
msg_kernel()
{
    const int n = blockIdx.z, h = blockIdx.y, lt = blockIdx.x;
    __shared__ float KVs[HD][HD];
    __shared__ float Kss[HD];

    const int tid = threadIdx.x;
    const size_t kvbase = (size_t)(n * NH + h) * HD * HD;
    for (int idx = tid; idx < HD * HD; idx += 128)
        KVs[idx >> 6][idx & 63] = g_KV[kvbase + idx];
    if (tid < HD) Kss[tid] = g_Ks[(n * NH + h) * HD + tid];
    __syncthreads();

    const int l = lt * 128 + tid;
    const size_t qbase = ((size_t)(n * LL + l)) * CC + h * HD;

    float acc[HD];
#pragma unroll
    for (int v = 0; v < HD; v++) acc[v] = 0.f;
    float zden = EPS_Z;

#pragma unroll
    for (int d0 = 0; d0 < HD; d0 += 4) {
        const float4 q4 = *(const float4*)(g_Q + qbase + d0);
        const float qv[4] = {q4.x, q4.y, q4.z, q4.w};
#pragma unroll
        for (int dd = 0; dd < 4; dd++) {
            const float q = qv[dd];
            zden = fmaf(q, Kss[d0 + dd], zden);
#pragma unroll
            for (int v0 = 0; v0 < HD; v0 += 4) {
                const float4 kv = *(const float4*)&KVs[d0 + dd][v0];
                acc[v0 + 0] = fmaf(q, kv.x, acc[v0 + 0]);
                acc[v0 + 1] = fmaf(q, kv.y, acc[v0 + 1]);
                acc[v0 + 2] = fmaf(q, kv.z, acc[v0 + 2]);
                acc[v0 + 3] = fmaf(q, kv.w, acc[v0 + 3]);
            }
        }
    }

    const float zs = (float)SEQS / zden;
#pragma unroll
    for (int v = 0; v < HD; v += 2) {
        const float r0 = acc[v] * zs, r1 = acc[v + 1] * zs;
        const __half h0 = __float2half_rn(r0);
        const __half h1 = __float2half_rn(r1);
        *(__half2*)(g_Mh + qbase + v) = __half2(h0, h1);
        *(__half2*)(g_Ml + qbase + v) =
            __half2(__float2half_rn(r0 - __half2float(h0)),
                    __float2half_rn(r1 - __half2float(h1)));
    }
}

// ---------------------------------------------------------------------------
// Block reduction helper (256 threads)
// ---------------------------------------------------------------------------
__device__ __forceinline__ float block_reduce_sum(float v)
{
    __shared__ float red[8];
    const int lane = threadIdx.x & 31, w = threadIdx.x >> 5;
#pragma unroll
    for (int o = 16; o; o >>= 1) v += __shfl_down_sync(0xffffffffu, v, o);
    if (lane == 0) red[w] = v;
    __syncthreads();
    float t = (threadIdx.x < 8) ? red[threadIdx.x] : 0.f;
    if (w == 0) {
#pragma unroll
        for (int o = 4; o; o >>= 1) t += __shfl_down_sync(0xffu, t, o);
        if (lane == 0) red[0] = t;
    }
    __syncthreads();
    float r = red[0];
    __syncthreads();
    return r;
}

// ---------------------------------------------------------------------------
// LN(M1) -> fp16 hi (message half of the concat; W1 is 1-pass).
// ---------------------------------------------------------------------------
__global__ void __launch_bounds__(256)
ln_split_kernel(const float* __restrict__ g, const float* __restrict__ b)
{
    const int row = blockIdx.x;
    __shared__ float buf[CC];
    const float* mr = g_M1 + (size_t)row * CC;
    const int tid = threadIdx.x;

    float s = 0.f;
    for (int c = tid; c < CC; c += 256) { float v = mr[c]; buf[c] = v; s += v; }
    const float mean = block_reduce_sum(s) * (1.f / CC);

    float vs = 0.f;
    for (int c = tid; c < CC; c += 256) { float d = buf[c] - mean; vs += d * d; }
    const float var  = block_reduce_sum(vs) * (1.f / CC);
    const float rstd = rsqrtf(var + LN_EPS);

    for (int c = tid; c < CC; c += 256) {
        const float lv = (buf[c] - mean) * rstd * g[c] + b[c];
        g_mlnh[(size_t)row * CC + c] = __float2half_rn(lv);
    }
}

// ---------------------------------------------------------------------------
// out = x + LN(M2). One block per row.
// ---------------------------------------------------------------------------
__global__ void __launch_bounds__(256)
ln_add_kernel(const float* __restrict__ x,
              const float* __restrict__ g, const float* __restrict__ b,
              float* __restrict__ out)
{
    const int row = blockIdx.x;
    __shared__ float buf[CC];
    const float* mr = g_M2 + (size_t)row * CC;
    const int tid = threadIdx.x;

    float s = 0.f;
    for (int c = tid; c < CC; c += 256) { float v = mr[c]; buf[c] = v; s += v; }
    const float mean = block_reduce_sum(s) * (1.f / CC);

    float vs = 0.f;
    for (int c = tid; c < CC; c += 256) { float d = buf[c] - mean; vs += d * d; }
    const float var  = block_reduce_sum(vs) * (1.f / CC);
    const float rstd = rsqrtf(var + LN_EPS);

    for (int c = tid; c < CC; c += 256) {
        out[(size_t)row * CC + c] =
            x[(size_t)row * CC + c] + (buf[c] - mean) * rstd * g[c] + b[c];
    }
}

// ---------------------------------------------------------------------------
// Launcher
// ---------------------------------------------------------------------------
extern "C" void kernel_launch(void* const* d_in, const int* in_sizes, int n_in,
                              void* d_out, int out_size)
{
    const float* x  = (const float*)d_in[0];
    const float* y  = (const float*)d_in[1];
    const float* Wq = (const float*)d_in[2];
    const float* Wk = (const float*)d_in[3];
    const float* Wv = (const float*)d_in[4];
    const float* Wm = (const float*)d_in[5];
    const float* W1 = (const float*)d_in[6];
    const float* W2 = (const float*)d_in[7];
    const float* g1 = (const float*)d_in[8];
    const float* b1 = (const float*)d_in[9];
    const float* g2 = (const float*)d_in[10];
    const float* b2 = (const float*)d_in[11];
    float* out = (float*)d_out;

    float *pQ, *pK, *pV, *pM1, *pM2;
    cudaGetSymbolAddress((void**)&pQ,  g_Q);
    cudaGetSymbolAddress((void**)&pK,  g_K);
    cudaGetSymbolAddress((void**)&pV,  g_V);
    cudaGetSymbolAddress((void**)&pM1, g_M1);
    cudaGetSymbolAddress((void**)&pM2, g_M2);

    __half *xh,*yh,*wqh,*wkh,*wvh,*wmh,*w1h,*w2h;
    __half *mh,*ml,*mlnh,*h1h;
    cudaGetSymbolAddress((void**)&xh,  g_xh);
    cudaGetSymbolAddress((void**)&yh,  g_yh);
    cudaGetSymbolAddress((void**)&wqh, g_Wqh);
    cudaGetSymbolAddress((void**)&wkh, g_Wkh);
    cudaGetSymbolAddress((void**)&wvh, g_Wvh);
    cudaGetSymbolAddress((void**)&wmh, g_Wmh);
    cudaGetSymbolAddress((void**)&w1h, g_W1h);
    cudaGetSymbolAddress((void**)&w2h, g_W2h);
    cudaGetSymbolAddress((void**)&mh,  g_Mh);  cudaGetSymbolAddress((void**)&ml,  g_Ml);
    cudaGetSymbolAddress((void**)&mlnh,g_mlnh);
    cudaGetSymbolAddress((void**)&h1h, g_H1h);

    cudaFuncSetAttribute(hmma_gemm<0,2>, cudaFuncAttributeMaxDynamicSharedMemorySize, SMEM_GEMM);
    cudaFuncSetAttribute(hmma_gemm<1,1>, cudaFuncAttributeMaxDynamicSharedMemorySize, SMEM_GEMM);
    cudaFuncSetAttribute(hmma_gemm<3,1>, cudaFuncAttributeMaxDynamicSharedMemorySize, SMEM_GEMM);
    cudaFuncSetAttribute(hmma_gemm<2,1>, cudaFuncAttributeMaxDynamicSharedMemorySize, SMEM_GEMM);
    cudaFuncSetAttribute(hmma_gemm<0,1>, cudaFuncAttributeMaxDynamicSharedMemorySize, SMEM_GEMM);

    // ---- one mega split launch (hi only everywhere)
    SplitJobs J;
    const float* srcs[NSPLIT] = {x, y, Wq, Wk, Wv, Wm, W1, W2};
    __half* his[NSPLIT] = {xh, yh, wqh, wkh, wvh, wmh, w1h, w2h};
    const int n4s[NSPLIT] = {NTOK * CC / 4, NTOK * CC / 4, CC * CC / 4, CC * CC / 4,
                             CC * CC / 4, CC * CC / 4, C2 * C2 / 4, CC * C2 / 4};
    int off = 0;
    for (int j = 0; j < NSPLIT; j++) {
        J.src[j] = srcs[j]; J.hi[j] = his[j]; J.n4[j] = n4s[j];
        J.blkoff[j] = off;
        off += (n4s[j] + 255) / 256;
    }
    J.blkoff[NSPLIT] = off;
    split_all<<<off, 256>>>(J);

    const dim3 gP  (CC / 128, NTOK / 128);      // 4 x 128
    const dim3 gKV (2 * CC / 128, NTOK / 128);  // 8 x 128 (K then V)
    const dim3 gW1 (C2 / 128, NTOK / 128);      // 8 x 128
    const size_t sC = (size_t)CC * 2, sC2 = (size_t)C2 * 2;

    // Q projection (1-pass, elu+1)
    hmma_gemm<1,1><<<gP, 256, SMEM_GEMM>>>(xh, xh, xh, xh, wqh, nullptr,
                                           pQ, nullptr, nullptr, CC, CC, 9999, sC, sC, 1.f);
    // K+V fused (1-pass): bx<4 -> K=elu(y@Wk)+1, bx>=4 -> V=(y@Wv)/S
    hmma_gemm<3,1><<<gKV, 256, SMEM_GEMM>>>(yh, yh, yh, yh, wkh, wvh,
                                            pK, pV, nullptr, CC, CC, 9999, sC, sC,
                                            1.f / (float)SEQS);

    zero_kv_kernel<<<(NB * NH * HD * HD + 255) / 256, 256>>>();
    kv_kernel<<<dim3(KV_SPLIT, NH, NB), 256>>>();
    msg_kernel<<<dim3(LL / 128, NH, NB), 128>>>();

    // Wm (2-pass: message has large dynamic range pre-LN)
    hmma_gemm<0,2><<<gP, 256, SMEM_GEMM>>>(mh, ml, mh, ml, wmh, nullptr,
                                           pM1, nullptr, nullptr, CC, CC, 9999, sC, sC, 1.f);
    ln_split_kernel<<<NTOK, 256>>>(g1, b1);
    // W1 (1-pass, relu -> fp16 hi): A = [x | LN(msg)] dual source
    hmma_gemm<2,1><<<gW1, 256, SMEM_GEMM>>>(xh, xh, mlnh, mlnh, w1h, nullptr,
                                            nullptr, nullptr, h1h, C2, C2, 16, sC, sC, 1.f);
    // W2 (1-pass)
    hmma_gemm<0,1><<<gP, 256, SMEM_GEMM>>>(h1h, h1h, h1h, h1h, w2h, nullptr,
                                           pM2, nullptr, nullptr, CC, C2, 9999, sC2, sC2, 1.f);
    ln_add_kernel<<<NTOK, 256>>>(x, g2, b2, out);
}

// round 10
// speedup vs baseline: 1.8052x; 1.1073x over previous
#include <cuda_runtime.h>
#include <cuda_fp16.h>
#include <math.h>
#include <stdint.h>

// ---------------------------------------------------------------------------
// Problem constants
// ---------------------------------------------------------------------------
#define NB   4
#define LL   4096
#define SEQS 4096
#define CC   512
#define NH   8
#define HD   64
#define C2   1024
#define NTOK (NB * LL)          // 16384
#define EPS_Z 1e-6f
#define LN_EPS 1e-5f

// ---------------------------------------------------------------------------
// Scratch (device globals; no allocation allowed)
// ---------------------------------------------------------------------------
__device__ __align__(16) float g_KV[NB * NH * HD * HD];
__device__ __align__(16) float g_Ks[NB * NH * HD];
__device__ __align__(16) float g_M1[(size_t)NTOK * CC];
__device__ __align__(16) float g_M2[(size_t)NTOK * CC];

// fp16 buffers
__device__ __align__(16) __half g_Qh[(size_t)NTOK * CC];
__device__ __align__(16) __half g_Kh[(size_t)NTOK * CC];
__device__ __align__(16) __half g_Vh[(size_t)NTOK * CC];
__device__ __align__(16) __half g_xh[(size_t)NTOK * CC];
__device__ __align__(16) __half g_yh[(size_t)NTOK * CC];
__device__ __align__(16) __half g_Wqh[CC * CC];
__device__ __align__(16) __half g_Wkh[CC * CC];
__device__ __align__(16) __half g_Wvh[CC * CC];
__device__ __align__(16) __half g_Wmh[CC * CC];
__device__ __align__(16) __half g_W1h[C2 * C2];
__device__ __align__(16) __half g_W2h[CC * C2];
__device__ __align__(16) __half g_Mh  [(size_t)NTOK * CC];
__device__ __align__(16) __half g_mlnh[(size_t)NTOK * CC];
__device__ __align__(16) __half g_H1h [(size_t)NTOK * C2];

// ---------------------------------------------------------------------------
// PTX helpers
// ---------------------------------------------------------------------------
__device__ __forceinline__ uint32_t smem_u32(const void* p)
{
    uint32_t a;
    asm("{ .reg .u64 t; cvta.to.shared.u64 t, %1; cvt.u32.u64 %0, t; }"
        : "=r"(a) : "l"(p));
    return a;
}

__device__ __forceinline__ void cpasync16(uint32_t dst, const void* src)
{
    asm volatile("cp.async.cg.shared.global [%0], [%1], 16;"
                 :: "r"(dst), "l"(src) : "memory");
}
__device__ __forceinline__ void cp_commit()
{
    asm volatile("cp.async.commit_group;" ::: "memory");
}
template <int N>
__device__ __forceinline__ void cp_wait()
{
    asm volatile("cp.async.wait_group %0;" :: "n"(N) : "memory");
}

__device__ __forceinline__ void ldm_x4(uint32_t& r0, uint32_t& r1,
                                       uint32_t& r2, uint32_t& r3, uint32_t a)
{
    asm volatile("ldmatrix.sync.aligned.m8n8.x4.shared.b16 {%0,%1,%2,%3}, [%4];"
                 : "=r"(r0), "=r"(r1), "=r"(r2), "=r"(r3) : "r"(a));
}

__device__ __forceinline__ void ldm_x4_t(uint32_t* r, uint32_t a)
{
    asm volatile("ldmatrix.sync.aligned.m8n8.x4.trans.shared.b16 {%0,%1,%2,%3}, [%4];"
                 : "=r"(r[0]), "=r"(r[1]), "=r"(r[2]), "=r"(r[3]) : "r"(a));
}

__device__ __forceinline__ void mma16816(float* c, const uint32_t* a,
                                         const uint32_t* b)
{
    asm volatile(
        "mma.sync.aligned.m16n8k16.row.col.f32.f16.f16.f32 "
        "{%0,%1,%2,%3}, {%4,%5,%6,%7}, {%8,%9}, {%0,%1,%2,%3};"
        : "+f"(c[0]), "+f"(c[1]), "+f"(c[2]), "+f"(c[3])
        : "r"(a[0]), "r"(a[1]), "r"(a[2]), "r"(a[3]), "r"(b[0]), "r"(b[1]));
}

// ---------------------------------------------------------------------------
// Mega split: fp32 -> fp16
// ---------------------------------------------------------------------------
#define NSPLIT 8
struct SplitJobs {
    const float* src[NSPLIT];
    __half* hi[NSPLIT];
    int n4[NSPLIT];
    int blkoff[NSPLIT + 1];
};

__global__ void __launch_bounds__(256)
split_all(SplitJobs J)
{
    int b = blockIdx.x;
    int j = 0;
#pragma unroll
    for (int t = 0; t < NSPLIT - 1; t++)
        if (b >= J.blkoff[t + 1]) j = t + 1;
    const int i = (b - J.blkoff[j]) * 256 + threadIdx.x;
    if (i >= J.n4[j]) return;
    float4 v = ((const float4*)J.src[j])[i];
    ((__half2*)J.hi[j])[i * 2 + 0] =
        __half2(__float2half_rn(v.x), __float2half_rn(v.y));
    ((__half2*)J.hi[j])[i * 2 + 1] =
        __half2(__float2half_rn(v.z), __float2half_rn(v.w));
}

// ---------------------------------------------------------------------------
// fp16 1-pass HMMA GEMM. Tile 128x128, BK=32 fp32-K, 4-stage cp.async,
// 8 warps 2x4, dual A-source (kSplit). EPI:
//   0 = scale -> f32 Cf
//   1 = elu+1 -> fp16 Ch
//   2 = relu  -> fp16 Ch
//   3 = fused KV: bx < gridDim.x/2 -> elu+1 -> Ch ; else -> *scale -> Ch2
// ---------------------------------------------------------------------------
#define ROWB   80
#define MATB   (128 * ROWB)       // 10240 B
#define STAGEB (2 * MATB)         // 20480 B (Ah, Bh)
#define NSTG   4
#define SMEM_GEMM (NSTG * STAGEB) // 81920 B

template <int EPI>
__global__ void __launch_bounds__(256, 2)
hmma_gemm(const __half* __restrict__ A1h, const __half* __restrict__ A2h,
          const __half* __restrict__ Bh, const __half* __restrict__ B2h,
          float* __restrict__ Cf, __half* __restrict__ Ch,
          __half* __restrict__ Ch2, int N, int K, int kSplit,
          size_t sA1b, size_t sA2b, float scale)
{
    extern __shared__ __align__(16) uint8_t dynsm[];
    const uint32_t sbase = smem_u32(dynsm);

    const int tid  = threadIdx.x;
    const int wid  = tid >> 5;
    const int lane = tid & 31;
    const int wr   = wid >> 2;
    const int wc   = wid & 3;
    const int bx   = blockIdx.x;
    const int by   = blockIdx.y;

    const int  halfx = (EPI == 3) ? ((int)gridDim.x >> 1) : 0;
    const bool isV   = (EPI == 3) && (bx >= halfx);
    const int  bn    = (EPI == 3) ? (isV ? bx - halfx : bx) : bx;
    const __half* Bsel = (EPI == 3 && isV) ? B2h : Bh;

    const int row0 = tid >> 2;               // 0..63
    const int cb   = (tid & 3) * 16;
    const size_t sBb = (size_t)K * 2;

    const char* gA1h = (const char*)A1h + (size_t)(by * 128 + row0) * sA1b + cb;
    const char* gA2h = (const char*)A2h + (size_t)(by * 128 + row0) * sA2b + cb;
    const char* gBh0 = (const char*)Bsel + (size_t)(bn * 128 + row0) * sBb + cb;
    const size_t rs1 = 64 * sA1b, rs2 = 64 * sA2b, rsB = 64 * sBb;

    const uint32_t dA0 = (uint32_t)(row0 * ROWB + cb);
    const uint32_t dA1 = (uint32_t)((row0 + 64) * ROWB + cb);

    auto issue = [&](int stage, int chunk) {
        const uint32_t s = sbase + stage * STAGEB;
        const char *ah; size_t o, rs;
        if (chunk < kSplit) { ah = gA1h; o = (size_t)chunk * 64; rs = rs1; }
        else { ah = gA2h; o = (size_t)(chunk - kSplit) * 64; rs = rs2; }
        cpasync16(s + dA0, ah + o);
        cpasync16(s + dA1, ah + o + rs);
        const size_t ob = (size_t)chunk * 64;
        cpasync16(s + MATB + dA0, gBh0 + ob);
        cpasync16(s + MATB + dA1, gBh0 + ob + rsB);
        cp_commit();
    };

    const uint32_t aRow = (uint32_t)(wr * 64 + (lane & 15));
    const uint32_t aCol = (uint32_t)((lane >> 4) << 4);
    const uint32_t bRow = (uint32_t)(wc * 32 + (lane & 7) + ((lane >> 4) << 3));
    const uint32_t bCol = (uint32_t)(((lane >> 3) & 1) << 4);

    float acc[4][4][4];
#pragma unroll
    for (int i = 0; i < 4; i++)
#pragma unroll
        for (int j = 0; j < 4; j++)
#pragma unroll
            for (int q = 0; q < 4; q++) acc[i][j][q] = 0.f;

    const int nch = K / 32;
    issue(0, 0);
    if (nch > 1) issue(1, 1);

    for (int c = 0; c < nch; c++) {
        if (c + 2 < nch) { issue((c + 2) % NSTG, c + 2); cp_wait<2>(); }
        else if (c + 1 < nch) { cp_wait<1>(); }
        else { cp_wait<0>(); }
        __syncthreads();

        const uint32_t s  = sbase + (c % NSTG) * STAGEB;
        const uint32_t pAh = s, pBh = s + MATB;

#pragma unroll
        for (int ks = 0; ks < 2; ks++) {
            const uint32_t kb = (uint32_t)(ks * 32);

            uint32_t ah[4][4], bh[2][4];
#pragma unroll
            for (int mi = 0; mi < 4; mi++)
                ldm_x4(ah[mi][0], ah[mi][1], ah[mi][2], ah[mi][3],
                       pAh + (aRow + mi * 16) * ROWB + kb + aCol);
#pragma unroll
            for (int ng = 0; ng < 2; ng++)
                ldm_x4(bh[ng][0], bh[ng][1], bh[ng][2], bh[ng][3],
                       pBh + (bRow + ng * 16) * ROWB + kb + bCol);
#pragma unroll
            for (int mi = 0; mi < 4; mi++)
#pragma unroll
                for (int ni = 0; ni < 4; ni++)
                    mma16816(acc[mi][ni], ah[mi], &bh[ni >> 1][(ni & 1) * 2]);
        }
        __syncthreads();
    }

    // ---- epilogue
#pragma unroll
    for (int mi = 0; mi < 4; mi++) {
#pragma unroll
        for (int ni = 0; ni < 4; ni++) {
            const int r = by * 128 + wr * 64 + mi * 16 + (lane >> 2);
            const int cn = bn * 128 + wc * 32 + ni * 8 + (lane & 3) * 2;
            float v0 = acc[mi][ni][0];
            float v1 = acc[mi][ni][1];
            float v2 = acc[mi][ni][2];
            float v3 = acc[mi][ni][3];
            if (EPI == 0 || (EPI == 3 && isV)) {
                v0 *= scale; v1 *= scale; v2 *= scale; v3 *= scale;
            }
            if (EPI == 1 || (EPI == 3 && !isV)) {
                v0 = (v0 > 0.f) ? (v0 + 1.f) : expf(v0);
                v1 = (v1 > 0.f) ? (v1 + 1.f) : expf(v1);
                v2 = (v2 > 0.f) ? (v2 + 1.f) : expf(v2);
                v3 = (v3 > 0.f) ? (v3 + 1.f) : expf(v3);
            }
            if (EPI == 2) {
                v0 = fmaxf(v0, 0.f); v1 = fmaxf(v1, 0.f);
                v2 = fmaxf(v2, 0.f); v3 = fmaxf(v3, 0.f);
            }

            if (EPI == 0) {
                *(float2*)(Cf + (size_t)r * N + cn) = make_float2(v0, v1);
                *(float2*)(Cf + (size_t)(r + 8) * N + cn) = make_float2(v2, v3);
            } else {
                __half* outp = (EPI == 3 && isV) ? Ch2 : Ch;
                *(__half2*)(outp + (size_t)r * N + cn) =
                    __half2(__float2half_rn(v0), __float2half_rn(v1));
                *(__half2*)(outp + (size_t)(r + 8) * N + cn) =
                    __half2(__float2half_rn(v2), __float2half_rn(v3));
            }
        }
    }
}

// ---------------------------------------------------------------------------
// Zero KV / Ksum accumulators
// ---------------------------------------------------------------------------
__global__ void zero_kv_kernel()
{
    int i = blockIdx.x * blockDim.x + threadIdx.x;
    if (i < NB * NH * HD * HD) g_KV[i] = 0.f;
    if (i < NB * NH * HD)      g_Ks[i] = 0.f;
}

// ---------------------------------------------------------------------------
// KV via tensor cores: KV[n,h] = K^T @ V over this block's s-range.
// K,V fp16 [NTOK, CC]; grid (KV_SPLIT, NH, NB); 256 thr = 8 warps 4(d)x2(v).
// A[d,s] and B[v,s] via ldmatrix.trans; fp32 accumulate; atomicAdd epilogue.
// Also accumulates Ksum[n,h,d] = sum_s K[s,d].
// ---------------------------------------------------------------------------
#define KV_SPLIT 16
#define KROWB  144                 // 64 halves (128B) + 16B pad
#define KTILEB (64 * KROWB)        // 9216 B

__global__ void __launch_bounds__(256)
kv_kernel()
{
    __shared__ __align__(16) uint8_t sm[4 * KTILEB];   // K0,V0,K1,V1
    const uint32_t sbase = smem_u32(sm);

    const int n = blockIdx.z, h = blockIdx.y, sp = blockIdx.x;
    const int s0 = sp * (SEQS / KV_SPLIT);             // 256 s per block
    const int tid  = threadIdx.x;
    const int wid  = tid >> 5;
    const int lane = tid & 31;
    const int d0   = (wid & 3) * 16;
    const int v0   = (wid >> 2) * 32;

    const char* gK = (const char*)g_Kh + ((size_t)(n * SEQS + s0) * CC + h * HD) * 2;
    const char* gV = (const char*)g_Vh + ((size_t)(n * SEQS + s0) * CC + h * HD) * 2;

    auto issue = [&](int stage, int chunk) {
        const uint32_t sK = sbase + stage * 2 * KTILEB;
        const uint32_t sV = sK + KTILEB;
        const size_t goff = (size_t)chunk * 64 * CC * 2;
#pragma unroll
        for (int i = 0; i < 2; i++) {
            const int slot = tid + i * 256;            // 0..511
            const int r  = slot >> 3;
            const int cc = (slot & 7) * 16;
            cpasync16(sK + r * KROWB + cc, gK + goff + (size_t)r * CC * 2 + cc);
            cpasync16(sV + r * KROWB + cc, gV + goff + (size_t)r * CC * 2 + cc);
        }
        cp_commit();
    };

    // trans-ldmatrix lane addressing
    const uint32_t aRow = (uint32_t)(((lane >> 4) << 3) + (lane & 7));   // s within 16
    const uint32_t aCol = (uint32_t)((d0 + ((lane >> 3) & 1) * 8) * 2);  // d bytes
    const uint32_t bRow = (uint32_t)((((lane >> 3) & 1) << 3) + (lane & 7));
    const uint32_t bColBase = (uint32_t)((v0 + (lane >> 4) * 8) * 2);

    float acc[4][4];
#pragma unroll
    for (int i = 0; i < 4; i++)
#pragma unroll
        for (int q = 0; q < 4; q++) acc[i][q] = 0.f;
    float ksacc = 0.f;

    issue(0, 0);
    const int nch = (SEQS / KV_SPLIT) / 64;            // 4

    for (int c = 0; c < nch; c++) {
        cp_wait<0>();
        __syncthreads();
        if (c + 1 < nch) issue((c + 1) & 1, c + 1);

        const uint32_t sK = sbase + (c & 1) * 2 * KTILEB;
        const uint32_t sV = sK + KTILEB;

#pragma unroll
        for (int ks = 0; ks < 4; ks++) {
            const uint32_t srow = (uint32_t)(ks * 16);
            uint32_t a[4], b0[4], b1[4];
            ldm_x4_t(a,  sK + (srow + aRow) * KROWB + aCol);
            ldm_x4_t(b0, sV + (srow + bRow) * KROWB + bColBase);
            ldm_x4_t(b1, sV + (srow + bRow) * KROWB + bColBase + 32); // +16 halves
            mma16816(acc[0], a, &b0[0]);
            mma16816(acc[1], a, &b0[2]);
            mma16816(acc[2], a, &b1[0]);
            mma16816(acc[3], a, &b1[2]);
        }

        if (tid < HD) {                                // Ksum: column tid
            const uint32_t base = sK + (uint32_t)(tid * 2);
#pragma unroll 8
            for (int s = 0; s < 64; s++)
                ksacc += __half2float(*(const __half*)(uintptr_t)
                         ((uintptr_t)sm + (base - sbase) + s * KROWB));
        }
        __syncthreads();
    }

    float* KVp = g_KV + (size_t)(n * NH + h) * HD * HD;
    const int dr = d0 + (lane >> 2);
    const int vc = (lane & 3) * 2;
#pragma unroll
    for (int ni = 0; ni < 4; ni++) {
        const int v = v0 + ni * 8 + vc;
        atomicAdd(&KVp[(size_t)dr * HD + v],           acc[ni][0]);
        atomicAdd(&KVp[(size_t)dr * HD + v + 1],       acc[ni][1]);
        atomicAdd(&KVp[(size_t)(dr + 8) * HD + v],     acc[ni][2]);
        atomicAdd(&KVp[(size_t)(dr + 8) * HD + v + 1], acc[ni][3]);
    }
    if (tid < HD)
        atomicAdd(&g_Ks[(n * NH + h) * HD + tid], ksacc);
}

// ---------------------------------------------------------------------------
// message: one thread per l-row, Q fp16, KV fp32 smem, no inner syncs.
// ---------------------------------------------------------------------------
__global__ void __launch_bounds__(128)
msg_kernel()
{
    const int n = blockIdx.z, h = blockIdx.y, lt = blockIdx.x;
    __shared__ float KVs[HD][HD];
    __shared__ float Kss[HD];

    const int tid = threadIdx.x;
    const size_t kvbase = (size_t)(n * NH + h) * HD * HD;
    for (int idx = tid; idx < HD * HD; idx += 128)
        KVs[idx >> 6][idx & 63] = g_KV[kvbase + idx];
    if (tid < HD) Kss[tid] = g_Ks[(n * NH + h) * HD + tid];
    __syncthreads();

    const int l = lt * 128 + tid;
    const size_t qbase = ((size_t)(n * LL + l)) * CC + h * HD;

    float acc[HD];
#pragma unroll
    for (int v = 0; v < HD; v++) acc[v] = 0.f;
    float zden = EPS_Z;

#pragma unroll
    for (int d0 = 0; d0 < HD; d0 += 4) {
        const uint2 qraw = *(const uint2*)(g_Qh + qbase + d0);
        const float2 f01 = __half22float2(*(const __half2*)&qraw.x);
        const float2 f23 = __half22float2(*(const __half2*)&qraw.y);
        const float qv[4] = {f01.x, f01.y, f23.x, f23.y};
#pragma unroll
        for (int dd = 0; dd < 4; dd++) {
            const float q = qv[dd];
            zden = fmaf(q, Kss[d0 + dd], zden);
#pragma unroll
            for (int v0 = 0; v0 < HD; v0 += 4) {
                const float4 kv = *(const float4*)&KVs[d0 + dd][v0];
                acc[v0 + 0] = fmaf(q, kv.x, acc[v0 + 0]);
                acc[v0 + 1] = fmaf(q, kv.y, acc[v0 + 1]);
                acc[v0 + 2] = fmaf(q, kv.z, acc[v0 + 2]);
                acc[v0 + 3] = fmaf(q, kv.w, acc[v0 + 3]);
            }
        }
    }

    const float zs = (float)SEQS / zden;
#pragma unroll
    for (int v = 0; v < HD; v += 2) {
        *(__half2*)(g_Mh + qbase + v) =
            __half2(__float2half_rn(acc[v] * zs), __float2half_rn(acc[v + 1] * zs));
    }
}

// ---------------------------------------------------------------------------
// Block reduction helper (256 threads)
// ---------------------------------------------------------------------------
__device__ __forceinline__ float block_reduce_sum(float v)
{
    __shared__ float red[8];
    const int lane = threadIdx.x & 31, w = threadIdx.x >> 5;
#pragma unroll
    for (int o = 16; o; o >>= 1) v += __shfl_down_sync(0xffffffffu, v, o);
    if (lane == 0) red[w] = v;
    __syncthreads();
    float t = (threadIdx.x < 8) ? red[threadIdx.x] : 0.f;
    if (w == 0) {
#pragma unroll
        for (int o = 4; o; o >>= 1) t += __shfl_down_sync(0xffu, t, o);
        if (lane == 0) red[0] = t;
    }
    __syncthreads();
    float r = red[0];
    __syncthreads();
    return r;
}

// ---------------------------------------------------------------------------
// LN(M1) -> fp16 (message half of the concat). One block per row.
// ---------------------------------------------------------------------------
__global__ void __launch_bounds__(256)
ln_split_kernel(const float* __restrict__ g, const float* __restrict__ b)
{
    const int row = blockIdx.x;
    __shared__ float buf[CC];
    const float* mr = g_M1 + (size_t)row * CC;
    const int tid = threadIdx.x;

    float s = 0.f;
    for (int c = tid; c < CC; c += 256) { float v = mr[c]; buf[c] = v; s += v; }
    const float mean = block_reduce_sum(s) * (1.f / CC);

    float vs = 0.f;
    for (int c = tid; c < CC; c += 256) { float d = buf[c] - mean; vs += d * d; }
    const float var  = block_reduce_sum(vs) * (1.f / CC);
    const float rstd = rsqrtf(var + LN_EPS);

    for (int c = tid; c < CC; c += 256) {
        const float lv = (buf[c] - mean) * rstd * g[c] + b[c];
        g_mlnh[(size_t)row * CC + c] = __float2half_rn(lv);
    }
}

// ---------------------------------------------------------------------------
// out = x + LN(M2). One block per row.
// ---------------------------------------------------------------------------
__global__ void __launch_bounds__(256)
ln_add_kernel(const float* __restrict__ x,
              const float* __restrict__ g, const float* __restrict__ b,
              float* __restrict__ out)
{
    const int row = blockIdx.x;
    __shared__ float buf[CC];
    const float* mr = g_M2 + (size_t)row * CC;
    const int tid = threadIdx.x;

    float s = 0.f;
    for (int c = tid; c < CC; c += 256) { float v = mr[c]; buf[c] = v; s += v; }
    const float mean = block_reduce_sum(s) * (1.f / CC);

    float vs = 0.f;
    for (int c = tid; c < CC; c += 256) { float d = buf[c] - mean; vs += d * d; }
    const float var  = block_reduce_sum(vs) * (1.f / CC);
    const float rstd = rsqrtf(var + LN_EPS);

    for (int c = tid; c < CC; c += 256) {
        out[(size_t)row * CC + c] =
            x[(size_t)row * CC + c] + (buf[c] - mean) * rstd * g[c] + b[c];
    }
}

// ---------------------------------------------------------------------------
// Launcher
// ---------------------------------------------------------------------------
extern "C" void kernel_launch(void* const* d_in, const int* in_sizes, int n_in,
                              void* d_out, int out_size)
{
    const float* x  = (const float*)d_in[0];
    const float* y  = (const float*)d_in[1];
    const float* Wq = (const float*)d_in[2];
    const float* Wk = (const float*)d_in[3];
    const float* Wv = (const float*)d_in[4];
    const float* Wm = (const float*)d_in[5];
    const float* W1 = (const float*)d_in[6];
    const float* W2 = (const float*)d_in[7];
    const float* g1 = (const float*)d_in[8];
    const float* b1 = (const float*)d_in[9];
    const float* g2 = (const float*)d_in[10];
    const float* b2 = (const float*)d_in[11];
    float* out = (float*)d_out;

    float *pM1, *pM2;
    cudaGetSymbolAddress((void**)&pM1, g_M1);
    cudaGetSymbolAddress((void**)&pM2, g_M2);

    __half *qh,*kh,*vh,*xh,*yh,*wqh,*wkh,*wvh,*wmh,*w1h,*w2h,*mh,*mlnh,*h1h;
    cudaGetSymbolAddress((void**)&qh,  g_Qh);
    cudaGetSymbolAddress((void**)&kh,  g_Kh);
    cudaGetSymbolAddress((void**)&vh,  g_Vh);
    cudaGetSymbolAddress((void**)&xh,  g_xh);
    cudaGetSymbolAddress((void**)&yh,  g_yh);
    cudaGetSymbolAddress((void**)&wqh, g_Wqh);
    cudaGetSymbolAddress((void**)&wkh, g_Wkh);
    cudaGetSymbolAddress((void**)&wvh, g_Wvh);
    cudaGetSymbolAddress((void**)&wmh, g_Wmh);
    cudaGetSymbolAddress((void**)&w1h, g_W1h);
    cudaGetSymbolAddress((void**)&w2h, g_W2h);
    cudaGetSymbolAddress((void**)&mh,  g_Mh);
    cudaGetSymbolAddress((void**)&mlnh,g_mlnh);
    cudaGetSymbolAddress((void**)&h1h, g_H1h);

    cudaFuncSetAttribute(hmma_gemm<0>, cudaFuncAttributeMaxDynamicSharedMemorySize, SMEM_GEMM);
    cudaFuncSetAttribute(hmma_gemm<1>, cudaFuncAttributeMaxDynamicSharedMemorySize, SMEM_GEMM);
    cudaFuncSetAttribute(hmma_gemm<2>, cudaFuncAttributeMaxDynamicSharedMemorySize, SMEM_GEMM);
    cudaFuncSetAttribute(hmma_gemm<3>, cudaFuncAttributeMaxDynamicSharedMemorySize, SMEM_GEMM);

    // ---- one mega split launch
    SplitJobs J;
    const float* srcs[NSPLIT] = {x, y, Wq, Wk, Wv, Wm, W1, W2};
    __half* his[NSPLIT] = {xh, yh, wqh, wkh, wvh, wmh, w1h, w2h};
    const int n4s[NSPLIT] = {NTOK * CC / 4, NTOK * CC / 4, CC * CC / 4, CC * CC / 4,
                             CC * CC / 4, CC * CC / 4, C2 * C2 / 4, CC * C2 / 4};
    int off = 0;
    for (int j = 0; j < NSPLIT; j++) {
        J.src[j] = srcs[j]; J.hi[j] = his[j]; J.n4[j] = n4s[j];
        J.blkoff[j] = off;
        off += (n4s[j] + 255) / 256;
    }
    J.blkoff[NSPLIT] = off;
    split_all<<<off, 256>>>(J);

    const dim3 gP  (CC / 128, NTOK / 128);      // 4 x 128
    const dim3 gKV (2 * CC / 128, NTOK / 128);  // 8 x 128 (K then V)
    const dim3 gW1 (C2 / 128, NTOK / 128);      // 8 x 128
    const size_t sC = (size_t)CC * 2, sC2 = (size_t)C2 * 2;

    // Q projection: elu+1 -> fp16
    hmma_gemm<1><<<gP, 256, SMEM_GEMM>>>(xh, xh, wqh, nullptr,
                                         nullptr, qh, nullptr, CC, CC, 9999, sC, sC, 1.f);
    // K+V fused: bx<4 -> K=elu(y@Wk)+1 fp16, bx>=4 -> V=(y@Wv)/S fp16
    hmma_gemm<3><<<gKV, 256, SMEM_GEMM>>>(yh, yh, wkh, wvh,
                                          nullptr, kh, vh, CC, CC, 9999, sC, sC,
                                          1.f / (float)SEQS);

    zero_kv_kernel<<<(NB * NH * HD * HD + 255) / 256, 256>>>();
    kv_kernel<<<dim3(KV_SPLIT, NH, NB), 256>>>();
    msg_kernel<<<dim3(LL / 128, NH, NB), 128>>>();

    // Wm: fp16 message -> f32 M1
    hmma_gemm<0><<<gP, 256, SMEM_GEMM>>>(mh, mh, wmh, nullptr,
                                         pM1, nullptr, nullptr, CC, CC, 9999, sC, sC, 1.f);
    ln_split_kernel<<<NTOK, 256>>>(g1, b1);
    // W1: relu -> fp16; A = [x | LN(msg)] dual source (chunks 0-15 x, 16-31 mln)
    hmma_gemm<2><<<gW1, 256, SMEM_GEMM>>>(xh, mlnh, w1h, nullptr,
                                          nullptr, h1h, nullptr, C2, C2, 16, sC, sC, 1.f);
    // W2 -> f32 M2
    hmma_gemm<0><<<gP, 256, SMEM_GEMM>>>(h1h, h1h, w2h, nullptr,
                                         pM2, nullptr, nullptr, CC, C2, 9999, sC2, sC2, 1.f);
    ln_add_kernel<<<NTOK, 256>>>(x, g2, b2, out);
}

// round 11
// speedup vs baseline: 1.9786x; 1.0961x over previous
#include <cuda_runtime.h>
#include <cuda_fp16.h>
#include <math.h>
#include <stdint.h>

// ---------------------------------------------------------------------------
// Problem constants
// ---------------------------------------------------------------------------
#define NB   4
#define LL   4096
#define SEQS 4096
#define CC   512
#define NH   8
#define HD   64
#define C2   1024
#define NTOK (NB * LL)          // 16384
#define EPS_Z 1e-6f
#define LN_EPS 1e-5f

// ---------------------------------------------------------------------------
// Scratch (device globals; no allocation allowed)
// ---------------------------------------------------------------------------
__device__ __align__(16) float g_KV[NB * NH * HD * HD];
__device__ __align__(16) float g_Ks[NB * NH * HD];
__device__ __align__(16) float g_M1[(size_t)NTOK * CC];
__device__ __align__(16) float g_M2[(size_t)NTOK * CC];

// fp16 buffers
__device__ __align__(16) __half g_Qh[(size_t)NTOK * CC];
__device__ __align__(16) __half g_Kh[(size_t)NTOK * CC];
__device__ __align__(16) __half g_Vh[(size_t)NTOK * CC];
__device__ __align__(16) __half g_KVTh[NB * NH * HD * HD];
__device__ __align__(16) __half g_xh[(size_t)NTOK * CC];
__device__ __align__(16) __half g_yh[(size_t)NTOK * CC];
__device__ __align__(16) __half g_Wqh[CC * CC];
__device__ __align__(16) __half g_Wkh[CC * CC];
__device__ __align__(16) __half g_Wvh[CC * CC];
__device__ __align__(16) __half g_Wmh[CC * CC];
__device__ __align__(16) __half g_W1h[C2 * C2];
__device__ __align__(16) __half g_W2h[CC * C2];
__device__ __align__(16) __half g_Mh  [(size_t)NTOK * CC];
__device__ __align__(16) __half g_mlnh[(size_t)NTOK * CC];
__device__ __align__(16) __half g_H1h [(size_t)NTOK * C2];

// ---------------------------------------------------------------------------
// PTX helpers
// ---------------------------------------------------------------------------
__device__ __forceinline__ uint32_t smem_u32(const void* p)
{
    uint32_t a;
    asm("{ .reg .u64 t; cvta.to.shared.u64 t, %1; cvt.u32.u64 %0, t; }"
        : "=r"(a) : "l"(p));
    return a;
}

__device__ __forceinline__ void cpasync16(uint32_t dst, const void* src)
{
    asm volatile("cp.async.cg.shared.global [%0], [%1], 16;"
                 :: "r"(dst), "l"(src) : "memory");
}
__device__ __forceinline__ void cp_commit()
{
    asm volatile("cp.async.commit_group;" ::: "memory");
}
template <int N>
__device__ __forceinline__ void cp_wait()
{
    asm volatile("cp.async.wait_group %0;" :: "n"(N) : "memory");
}

__device__ __forceinline__ void ldm_x4(uint32_t& r0, uint32_t& r1,
                                       uint32_t& r2, uint32_t& r3, uint32_t a)
{
    asm volatile("ldmatrix.sync.aligned.m8n8.x4.shared.b16 {%0,%1,%2,%3}, [%4];"
                 : "=r"(r0), "=r"(r1), "=r"(r2), "=r"(r3) : "r"(a));
}

__device__ __forceinline__ void ldm_x4p(uint32_t* r, uint32_t a)
{
    asm volatile("ldmatrix.sync.aligned.m8n8.x4.shared.b16 {%0,%1,%2,%3}, [%4];"
                 : "=r"(r[0]), "=r"(r[1]), "=r"(r[2]), "=r"(r[3]) : "r"(a));
}

__device__ __forceinline__ void ldm_x4_t(uint32_t* r, uint32_t a)
{
    asm volatile("ldmatrix.sync.aligned.m8n8.x4.trans.shared.b16 {%0,%1,%2,%3}, [%4];"
                 : "=r"(r[0]), "=r"(r[1]), "=r"(r[2]), "=r"(r[3]) : "r"(a));
}

__device__ __forceinline__ void mma16816(float* c, const uint32_t* a,
                                         const uint32_t* b)
{
    asm volatile(
        "mma.sync.aligned.m16n8k16.row.col.f32.f16.f16.f32 "
        "{%0,%1,%2,%3}, {%4,%5,%6,%7}, {%8,%9}, {%0,%1,%2,%3};"
        : "+f"(c[0]), "+f"(c[1]), "+f"(c[2]), "+f"(c[3])
        : "r"(a[0]), "r"(a[1]), "r"(a[2]), "r"(a[3]), "r"(b[0]), "r"(b[1]));
}

// ---------------------------------------------------------------------------
// Mega split: fp32 -> fp16
// ---------------------------------------------------------------------------
#define NSPLIT 8
struct SplitJobs {
    const float* src[NSPLIT];
    __half* hi[NSPLIT];
    int n4[NSPLIT];
    int blkoff[NSPLIT + 1];
};

__global__ void __launch_bounds__(256)
split_all(SplitJobs J)
{
    int b = blockIdx.x;
    int j = 0;
#pragma unroll
    for (int t = 0; t < NSPLIT - 1; t++)
        if (b >= J.blkoff[t + 1]) j = t + 1;
    const int i = (b - J.blkoff[j]) * 256 + threadIdx.x;
    if (i >= J.n4[j]) return;
    float4 v = ((const float4*)J.src[j])[i];
    ((__half2*)J.hi[j])[i * 2 + 0] =
        __half2(__float2half_rn(v.x), __float2half_rn(v.y));
    ((__half2*)J.hi[j])[i * 2 + 1] =
        __half2(__float2half_rn(v.z), __float2half_rn(v.w));
}

// ---------------------------------------------------------------------------
// fp16 1-pass HMMA GEMM. Tile 128x128, BK=32 fp32-K, 4-stage cp.async,
// 8 warps 2x4, dual A-source (kSplit). EPI:
//   0 = scale -> f32 Cf
//   2 = relu  -> fp16 Ch
//   4 = merged QKV: seg=bx>>2: 0 -> elu(A1@Bh)->Ch, 1 -> elu(A2@B2h)->Ch2,
//                   2 -> (A2@B3h)*scale -> Ch3
// ---------------------------------------------------------------------------
#define ROWB   80
#define MATB   (128 * ROWB)       // 10240 B
#define STAGEB (2 * MATB)         // 20480 B (Ah, Bh)
#define NSTG   4
#define SMEM_GEMM (NSTG * STAGEB) // 81920 B

template <int EPI>
__global__ void __launch_bounds__(256, 2)
hmma_gemm(const __half* __restrict__ A1h, const __half* __restrict__ A2h,
          const __half* __restrict__ Bh, const __half* __restrict__ B2h,
          const __half* __restrict__ B3h,
          float* __restrict__ Cf, __half* __restrict__ Ch,
          __half* __restrict__ Ch2, __half* __restrict__ Ch3,
          int N, int K, int kSplit,
          size_t sA1b, size_t sA2b, float scale)
{
    extern __shared__ __align__(16) uint8_t dynsm[];
    const uint32_t sbase = smem_u32(dynsm);

    const int tid  = threadIdx.x;
    const int wid  = tid >> 5;
    const int lane = tid & 31;
    const int wr   = wid >> 2;
    const int wc   = wid & 3;
    const int bx   = blockIdx.x;
    const int by   = blockIdx.y;

    const int seg = (EPI == 4) ? (bx >> 2) : 0;
    const int bn  = (EPI == 4) ? (bx & 3) : bx;
    const __half* Bsel = Bh;
    if (EPI == 4) Bsel = (seg == 0) ? Bh : ((seg == 1) ? B2h : B3h);
    const int kS = (EPI == 4) ? ((seg == 0) ? 9999 : 0) : kSplit;

    const int row0 = tid >> 2;               // 0..63
    const int cb   = (tid & 3) * 16;
    const size_t sBb = (size_t)K * 2;

    const char* gA1h = (const char*)A1h + (size_t)(by * 128 + row0) * sA1b + cb;
    const char* gA2h = (const char*)A2h + (size_t)(by * 128 + row0) * sA2b + cb;
    const char* gBh0 = (const char*)Bsel + (size_t)(bn * 128 + row0) * sBb + cb;
    const size_t rs1 = 64 * sA1b, rs2 = 64 * sA2b, rsB = 64 * sBb;

    const uint32_t dA0 = (uint32_t)(row0 * ROWB + cb);
    const uint32_t dA1 = (uint32_t)((row0 + 64) * ROWB + cb);

    auto issue = [&](int stage, int chunk) {
        const uint32_t s = sbase + stage * STAGEB;
        const char *ah; size_t o, rs;
        if (chunk < kS) { ah = gA1h; o = (size_t)chunk * 64; rs = rs1; }
        else { ah = gA2h; o = (size_t)(chunk - kS) * 64; rs = rs2; }
        cpasync16(s + dA0, ah + o);
        cpasync16(s + dA1, ah + o + rs);
        const size_t ob = (size_t)chunk * 64;
        cpasync16(s + MATB + dA0, gBh0 + ob);
        cpasync16(s + MATB + dA1, gBh0 + ob + rsB);
        cp_commit();
    };

    const uint32_t aRow = (uint32_t)(wr * 64 + (lane & 15));
    const uint32_t aCol = (uint32_t)((lane >> 4) << 4);
    const uint32_t bRow = (uint32_t)(wc * 32 + (lane & 7) + ((lane >> 4) << 3));
    const uint32_t bCol = (uint32_t)(((lane >> 3) & 1) << 4);

    float acc[4][4][4];
#pragma unroll
    for (int i = 0; i < 4; i++)
#pragma unroll
        for (int j = 0; j < 4; j++)
#pragma unroll
            for (int q = 0; q < 4; q++) acc[i][j][q] = 0.f;

    const int nch = K / 32;
    issue(0, 0);
    if (nch > 1) issue(1, 1);

    for (int c = 0; c < nch; c++) {
        if (c + 2 < nch) { issue((c + 2) % NSTG, c + 2); cp_wait<2>(); }
        else if (c + 1 < nch) { cp_wait<1>(); }
        else { cp_wait<0>(); }
        __syncthreads();

        const uint32_t s  = sbase + (c % NSTG) * STAGEB;
        const uint32_t pAh = s, pBh = s + MATB;

#pragma unroll
        for (int ks = 0; ks < 2; ks++) {
            const uint32_t kb = (uint32_t)(ks * 32);

            uint32_t ah[4][4], bh[2][4];
#pragma unroll
            for (int mi = 0; mi < 4; mi++)
                ldm_x4(ah[mi][0], ah[mi][1], ah[mi][2], ah[mi][3],
                       pAh + (aRow + mi * 16) * ROWB + kb + aCol);
#pragma unroll
            for (int ng = 0; ng < 2; ng++)
                ldm_x4(bh[ng][0], bh[ng][1], bh[ng][2], bh[ng][3],
                       pBh + (bRow + ng * 16) * ROWB + kb + bCol);
#pragma unroll
            for (int mi = 0; mi < 4; mi++)
#pragma unroll
                for (int ni = 0; ni < 4; ni++)
                    mma16816(acc[mi][ni], ah[mi], &bh[ni >> 1][(ni & 1) * 2]);
        }
        __syncthreads();
    }

    // ---- epilogue
#pragma unroll
    for (int mi = 0; mi < 4; mi++) {
#pragma unroll
        for (int ni = 0; ni < 4; ni++) {
            const int r = by * 128 + wr * 64 + mi * 16 + (lane >> 2);
            const int cn = bn * 128 + wc * 32 + ni * 8 + (lane & 3) * 2;
            float v0 = acc[mi][ni][0];
            float v1 = acc[mi][ni][1];
            float v2 = acc[mi][ni][2];
            float v3 = acc[mi][ni][3];
            if (EPI == 0 || (EPI == 4 && seg == 2)) {
                v0 *= scale; v1 *= scale; v2 *= scale; v3 *= scale;
            }
            if (EPI == 4 && seg < 2) {
                v0 = (v0 > 0.f) ? (v0 + 1.f) : expf(v0);
                v1 = (v1 > 0.f) ? (v1 + 1.f) : expf(v1);
                v2 = (v2 > 0.f) ? (v2 + 1.f) : expf(v2);
                v3 = (v3 > 0.f) ? (v3 + 1.f) : expf(v3);
            }
            if (EPI == 2) {
                v0 = fmaxf(v0, 0.f); v1 = fmaxf(v1, 0.f);
                v2 = fmaxf(v2, 0.f); v3 = fmaxf(v3, 0.f);
            }

            if (EPI == 0) {
                *(float2*)(Cf + (size_t)r * N + cn) = make_float2(v0, v1);
                *(float2*)(Cf + (size_t)(r + 8) * N + cn) = make_float2(v2, v3);
            } else {
                __half* outp = Ch;
                if (EPI == 4) outp = (seg == 0) ? Ch : ((seg == 1) ? Ch2 : Ch3);
                *(__half2*)(outp + (size_t)r * N + cn) =
                    __half2(__float2half_rn(v0), __float2half_rn(v1));
                *(__half2*)(outp + (size_t)(r + 8) * N + cn) =
                    __half2(__float2half_rn(v2), __float2half_rn(v3));
            }
        }
    }
}

// ---------------------------------------------------------------------------
// Zero KV / Ksum accumulators
// ---------------------------------------------------------------------------
__global__ void zero_kv_kernel()
{
    int i = blockIdx.x * blockDim.x + threadIdx.x;
    if (i < NB * NH * HD * HD) g_KV[i] = 0.f;
    if (i < NB * NH * HD)      g_Ks[i] = 0.f;
}

// ---------------------------------------------------------------------------
// KV via tensor cores: KV[n,h] = K^T @ V (+ Ksum) over this block's s-range.
// ---------------------------------------------------------------------------
#define KV_SPLIT 16
#define KROWB  144
#define KTILEB (64 * KROWB)

__global__ void __launch_bounds__(256)
kv_kernel()
{
    __shared__ __align__(16) uint8_t sm[4 * KTILEB];   // K0,V0,K1,V1
    const uint32_t sbase = smem_u32(sm);

    const int n = blockIdx.z, h = blockIdx.y, sp = blockIdx.x;
    const int s0 = sp * (SEQS / KV_SPLIT);
    const int tid  = threadIdx.x;
    const int wid  = tid >> 5;
    const int lane = tid & 31;
    const int d0   = (wid & 3) * 16;
    const int v0   = (wid >> 2) * 32;

    const char* gK = (const char*)g_Kh + ((size_t)(n * SEQS + s0) * CC + h * HD) * 2;
    const char* gV = (const char*)g_Vh + ((size_t)(n * SEQS + s0) * CC + h * HD) * 2;

    auto issue = [&](int stage, int chunk) {
        const uint32_t sK = sbase + stage * 2 * KTILEB;
        const uint32_t sV = sK + KTILEB;
        const size_t goff = (size_t)chunk * 64 * CC * 2;
#pragma unroll
        for (int i = 0; i < 2; i++) {
            const int slot = tid + i * 256;
            const int r  = slot >> 3;
            const int cc = (slot & 7) * 16;
            cpasync16(sK + r * KROWB + cc, gK + goff + (size_t)r * CC * 2 + cc);
            cpasync16(sV + r * KROWB + cc, gV + goff + (size_t)r * CC * 2 + cc);
        }
        cp_commit();
    };

    const uint32_t aRow = (uint32_t)(((lane >> 4) << 3) + (lane & 7));
    const uint32_t aCol = (uint32_t)((d0 + ((lane >> 3) & 1) * 8) * 2);
    const uint32_t bRow = (uint32_t)((((lane >> 3) & 1) << 3) + (lane & 7));
    const uint32_t bColBase = (uint32_t)((v0 + (lane >> 4) * 8) * 2);

    float acc[4][4];
#pragma unroll
    for (int i = 0; i < 4; i++)
#pragma unroll
        for (int q = 0; q < 4; q++) acc[i][q] = 0.f;
    float ksacc = 0.f;

    issue(0, 0);
    const int nch = (SEQS / KV_SPLIT) / 64;

    for (int c = 0; c < nch; c++) {
        cp_wait<0>();
        __syncthreads();
        if (c + 1 < nch) issue((c + 1) & 1, c + 1);

        const uint32_t sK = sbase + (c & 1) * 2 * KTILEB;
        const uint32_t sV = sK + KTILEB;

#pragma unroll
        for (int ks = 0; ks < 4; ks++) {
            const uint32_t srow = (uint32_t)(ks * 16);
            uint32_t a[4], b0[4], b1[4];
            ldm_x4_t(a,  sK + (srow + aRow) * KROWB + aCol);
            ldm_x4_t(b0, sV + (srow + bRow) * KROWB + bColBase);
            ldm_x4_t(b1, sV + (srow + bRow) * KROWB + bColBase + 32);
            mma16816(acc[0], a, &b0[0]);
            mma16816(acc[1], a, &b0[2]);
            mma16816(acc[2], a, &b1[0]);
            mma16816(acc[3], a, &b1[2]);
        }

        if (tid < HD) {
            const uint32_t boff = (c & 1) * 2 * KTILEB + (uint32_t)(tid * 2);
#pragma unroll 8
            for (int s = 0; s < 64; s++)
                ksacc += __half2float(*(const __half*)(sm + boff + s * KROWB));
        }
        __syncthreads();
    }

    float* KVp = g_KV + (size_t)(n * NH + h) * HD * HD;
    const int dr = d0 + (lane >> 2);
    const int vc = (lane & 3) * 2;
#pragma unroll
    for (int ni = 0; ni < 4; ni++) {
        const int v = v0 + ni * 8 + vc;
        atomicAdd(&KVp[(size_t)dr * HD + v],           acc[ni][0]);
        atomicAdd(&KVp[(size_t)dr * HD + v + 1],       acc[ni][1]);
        atomicAdd(&KVp[(size_t)(dr + 8) * HD + v],     acc[ni][2]);
        atomicAdd(&KVp[(size_t)(dr + 8) * HD + v + 1], acc[ni][3]);
    }
    if (tid < HD)
        atomicAdd(&g_Ks[(n * NH + h) * HD + tid], ksacc);
}

// ---------------------------------------------------------------------------
// KVT: fp32 KV[d][v] -> fp16 KVT[v][d] per (n,h)
// ---------------------------------------------------------------------------
__global__ void __launch_bounds__(256)
kvt_kernel()
{
    const int nh = blockIdx.x;
    const float* src = g_KV + (size_t)nh * HD * HD;
    __half* dst = g_KVTh + (size_t)nh * HD * HD;
    for (int i = threadIdx.x; i < HD * HD; i += 256) {
        const int v = i >> 6, d = i & 63;
        dst[i] = __float2half_rn(src[d * HD + v]);
    }
}

// ---------------------------------------------------------------------------
// msg via tensor cores: per (n,h,128-l-tile):
//   M[l, h*64+v] = S * (Q[l,:] @ KVT[v,:]) / (Q[l,:] . Ksum + eps)
// 128 threads (4 warps, 32 rows each). Single-shot smem load (K=64).
// ---------------------------------------------------------------------------
#define MROWB 144
__global__ void __launch_bounds__(128)
msg_tc_kernel()
{
    __shared__ __align__(16) uint8_t smQ[128 * MROWB];
    __shared__ __align__(16) uint8_t smB[64 * MROWB];
    __shared__ float Kss[HD];

    const int n = blockIdx.z, h = blockIdx.y, lt = blockIdx.x;
    const int tid  = threadIdx.x;
    const int wr   = tid >> 5;
    const int lane = tid & 31;

    const uint32_t sQ = smem_u32(smQ);
    const uint32_t sB = smem_u32(smB);

    const char* gQ = (const char*)g_Qh +
        ((size_t)(n * LL + lt * 128) * CC + h * HD) * 2;
    const char* gB = (const char*)g_KVTh + (size_t)(n * NH + h) * HD * HD * 2;

    // load Q tile: 128 rows x 128B = 1024 x 16B
#pragma unroll
    for (int i = 0; i < 8; i++) {
        const int slot = tid + i * 128;
        const int r = slot >> 3, c = (slot & 7) * 16;
        cpasync16(sQ + r * MROWB + c, gQ + (size_t)r * CC * 2 + c);
    }
    // load KVT: 64 rows x 128B = 512 x 16B
#pragma unroll
    for (int i = 0; i < 4; i++) {
        const int slot = tid + i * 128;
        const int r = slot >> 3, c = (slot & 7) * 16;
        cpasync16(sB + r * MROWB + c, gB + (size_t)r * HD * 2 + c);
    }
    cp_commit();
    if (tid < HD) Kss[tid] = g_Ks[(n * NH + h) * HD + tid];
    cp_wait<0>();
    __syncthreads();

    const uint32_t aRow = (uint32_t)(wr * 32 + (lane & 15));
    const uint32_t aCol = (uint32_t)((lane >> 4) << 4);
    const uint32_t bRow = (uint32_t)((lane & 7) + ((lane >> 4) << 3));
    const uint32_t bCol = (uint32_t)(((lane >> 3) & 1) << 4);

    float acc[2][8][4];
#pragma unroll
    for (int i = 0; i < 2; i++)
#pragma unroll
        for (int j = 0; j < 8; j++)
#pragma unroll
            for (int q = 0; q < 4; q++) acc[i][j][q] = 0.f;

#pragma unroll
    for (int ks = 0; ks < 4; ks++) {
        const uint32_t kb = (uint32_t)(ks * 32);
        uint32_t a[2][4], b[4][4];
#pragma unroll
        for (int mi = 0; mi < 2; mi++)
            ldm_x4p(a[mi], sQ + (aRow + mi * 16) * MROWB + kb + aCol);
#pragma unroll
        for (int ng = 0; ng < 4; ng++)
            ldm_x4p(b[ng], sB + (ng * 16 + bRow) * MROWB + kb + bCol);
#pragma unroll
        for (int mi = 0; mi < 2; mi++)
#pragma unroll
            for (int ni = 0; ni < 8; ni++)
                mma16816(acc[mi][ni], a[mi], &b[ni >> 1][(ni & 1) * 2]);
    }

    // epilogue: per-row zden then scaled fp16 store
#pragma unroll
    for (int mi = 0; mi < 2; mi++) {
        const int r0 = wr * 32 + mi * 16 + (lane >> 2);   // local rows r0, r0+8
        float zd0 = EPS_Z, zd1 = EPS_Z;
        const __half2* q0 = (const __half2*)(smQ + r0 * MROWB);
        const __half2* q1 = (const __half2*)(smQ + (r0 + 8) * MROWB);
#pragma unroll
        for (int k = 0; k < HD / 2; k++) {
            const float2 a0 = __half22float2(q0[k]);
            const float2 a1 = __half22float2(q1[k]);
            zd0 = fmaf(a0.x, Kss[2 * k], fmaf(a0.y, Kss[2 * k + 1], zd0));
            zd1 = fmaf(a1.x, Kss[2 * k], fmaf(a1.y, Kss[2 * k + 1], zd1));
        }
        const float zs0 = (float)SEQS / zd0;
        const float zs1 = (float)SEQS / zd1;

        const size_t base0 = ((size_t)(n * LL + lt * 128 + r0)) * CC + h * HD;
        const size_t base1 = base0 + (size_t)8 * CC;
#pragma unroll
        for (int ni = 0; ni < 8; ni++) {
            const int cn = ni * 8 + (lane & 3) * 2;
            *(__half2*)(g_Mh + base0 + cn) =
                __half2(__float2half_rn(acc[mi][ni][0] * zs0),
                        __float2half_rn(acc[mi][ni][1] * zs0));
            *(__half2*)(g_Mh + base1 + cn) =
                __half2(__float2half_rn(acc[mi][ni][2] * zs1),
                        __float2half_rn(acc[mi][ni][3] * zs1));
        }
    }
}

// ---------------------------------------------------------------------------
// Block reduction helper (256 threads)
// ---------------------------------------------------------------------------
__device__ __forceinline__ float block_reduce_sum(float v)
{
    __shared__ float red[8];
    const int lane = threadIdx.x & 31, w = threadIdx.x >> 5;
#pragma unroll
    for (int o = 16; o; o >>= 1) v += __shfl_down_sync(0xffffffffu, v, o);
    if (lane == 0) red[w] = v;
    __syncthreads();
    float t = (threadIdx.x < 8) ? red[threadIdx.x] : 0.f;
    if (w == 0) {
#pragma unroll
        for (int o = 4; o; o >>= 1) t += __shfl_down_sync(0xffu, t, o);
        if (lane == 0) red[0] = t;
    }
    __syncthreads();
    float r = red[0];
    __syncthreads();
    return r;
}

// ---------------------------------------------------------------------------
// LN(M1) -> fp16 (message half of the concat). One block per row.
// ---------------------------------------------------------------------------
__global__ void __launch_bounds__(256)
ln_split_kernel(const float* __restrict__ g, const float* __restrict__ b)
{
    const int row = blockIdx.x;
    __shared__ float buf[CC];
    const float* mr = g_M1 + (size_t)row * CC;
    const int tid = threadIdx.x;

    float s = 0.f;
    for (int c = tid; c < CC; c += 256) { float v = mr[c]; buf[c] = v; s += v; }
    const float mean = block_reduce_sum(s) * (1.f / CC);

    float vs = 0.f;
    for (int c = tid; c < CC; c += 256) { float d = buf[c] - mean; vs += d * d; }
    const float var  = block_reduce_sum(vs) * (1.f / CC);
    const float rstd = rsqrtf(var + LN_EPS);

    for (int c = tid; c < CC; c += 256) {
        const float lv = (buf[c] - mean) * rstd * g[c] + b[c];
        g_mlnh[(size_t)row * CC + c] = __float2half_rn(lv);
    }
}

// ---------------------------------------------------------------------------
// out = x + LN(M2). One block per row.
// ---------------------------------------------------------------------------
__global__ void __launch_bounds__(256)
ln_add_kernel(const float* __restrict__ x,
              const float* __restrict__ g, const float* __restrict__ b,
              float* __restrict__ out)
{
    const int row = blockIdx.x;
    __shared__ float buf[CC];
    const float* mr = g_M2 + (size_t)row * CC;
    const int tid = threadIdx.x;

    float s = 0.f;
    for (int c = tid; c < CC; c += 256) { float v = mr[c]; buf[c] = v; s += v; }
    const float mean = block_reduce_sum(s) * (1.f / CC);

    float vs = 0.f;
    for (int c = tid; c < CC; c += 256) { float d = buf[c] - mean; vs += d * d; }
    const float var  = block_reduce_sum(vs) * (1.f / CC);
    const float rstd = rsqrtf(var + LN_EPS);

    for (int c = tid; c < CC; c += 256) {
        out[(size_t)row * CC + c] =
            x[(size_t)row * CC + c] + (buf[c] - mean) * rstd * g[c] + b[c];
    }
}

// ---------------------------------------------------------------------------
// Launcher
// ---------------------------------------------------------------------------
extern "C" void kernel_launch(void* const* d_in, const int* in_sizes, int n_in,
                              void* d_out, int out_size)
{
    const float* x  = (const float*)d_in[0];
    const float* y  = (const float*)d_in[1];
    const float* Wq = (const float*)d_in[2];
    const float* Wk = (const float*)d_in[3];
    const float* Wv = (const float*)d_in[4];
    const float* Wm = (const float*)d_in[5];
    const float* W1 = (const float*)d_in[6];
    const float* W2 = (const float*)d_in[7];
    const float* g1 = (const float*)d_in[8];
    const float* b1 = (const float*)d_in[9];
    const float* g2 = (const float*)d_in[10];
    const float* b2 = (const float*)d_in[11];
    float* out = (float*)d_out;

    float *pM1, *pM2;
    cudaGetSymbolAddress((void**)&pM1, g_M1);
    cudaGetSymbolAddress((void**)&pM2, g_M2);

    __half *qh,*kh,*vh,*xh,*yh,*wqh,*wkh,*wvh,*wmh,*w1h,*w2h,*mh,*mlnh,*h1h;
    cudaGetSymbolAddress((void**)&qh,  g_Qh);
    cudaGetSymbolAddress((void**)&kh,  g_Kh);
    cudaGetSymbolAddress((void**)&vh,  g_Vh);
    cudaGetSymbolAddress((void**)&xh,  g_xh);
    cudaGetSymbolAddress((void**)&yh,  g_yh);
    cudaGetSymbolAddress((void**)&wqh, g_Wqh);
    cudaGetSymbolAddress((void**)&wkh, g_Wkh);
    cudaGetSymbolAddress((void**)&wvh, g_Wvh);
    cudaGetSymbolAddress((void**)&wmh, g_Wmh);
    cudaGetSymbolAddress((void**)&w1h, g_W1h);
    cudaGetSymbolAddress((void**)&w2h, g_W2h);
    cudaGetSymbolAddress((void**)&mh,  g_Mh);
    cudaGetSymbolAddress((void**)&mlnh,g_mlnh);
    cudaGetSymbolAddress((void**)&h1h, g_H1h);

    cudaFuncSetAttribute(hmma_gemm<0>, cudaFuncAttributeMaxDynamicSharedMemorySize, SMEM_GEMM);
    cudaFuncSetAttribute(hmma_gemm<2>, cudaFuncAttributeMaxDynamicSharedMemorySize, SMEM_GEMM);
    cudaFuncSetAttribute(hmma_gemm<4>, cudaFuncAttributeMaxDynamicSharedMemorySize, SMEM_GEMM);

    // ---- one mega split launch
    SplitJobs J;
    const float* srcs[NSPLIT] = {x, y, Wq, Wk, Wv, Wm, W1, W2};
    __half* his[NSPLIT] = {xh, yh, wqh, wkh, wvh, wmh, w1h, w2h};
    const int n4s[NSPLIT] = {NTOK * CC / 4, NTOK * CC / 4, CC * CC / 4, CC * CC / 4,
                             CC * CC / 4, CC * CC / 4, C2 * C2 / 4, CC * C2 / 4};
    int off = 0;
    for (int j = 0; j < NSPLIT; j++) {
        J.src[j] = srcs[j]; J.hi[j] = his[j]; J.n4[j] = n4s[j];
        J.blkoff[j] = off;
        off += (n4s[j] + 255) / 256;
    }
    J.blkoff[NSPLIT] = off;
    split_all<<<off, 256>>>(J);

    const dim3 gQKV(3 * CC / 128, NTOK / 128);  // 12 x 128 (Q, K, V)
    const dim3 gP  (CC / 128, NTOK / 128);      // 4 x 128
    const dim3 gW1 (C2 / 128, NTOK / 128);      // 8 x 128
    const size_t sC = (size_t)CC * 2, sC2 = (size_t)C2 * 2;

    // merged Q,K,V projections
    hmma_gemm<4><<<gQKV, 256, SMEM_GEMM>>>(xh, yh, wqh, wkh, wvh,
                                           nullptr, qh, kh, vh, CC, CC, 9999,
                                           sC, sC, 1.f / (float)SEQS);

    zero_kv_kernel<<<(NB * NH * HD * HD + 255) / 256, 256>>>();
    kv_kernel<<<dim3(KV_SPLIT, NH, NB), 256>>>();
    kvt_kernel<<<NB * NH, 256>>>();
    msg_tc_kernel<<<dim3(LL / 128, NH, NB), 128>>>();

    // Wm: fp16 message -> f32 M1
    hmma_gemm<0><<<gP, 256, SMEM_GEMM>>>(mh, mh, wmh, nullptr, nullptr,
                                         pM1, nullptr, nullptr, nullptr,
                                         CC, CC, 9999, sC, sC, 1.f);
    ln_split_kernel<<<NTOK, 256>>>(g1, b1);
    // W1: relu -> fp16; A = [x | LN(msg)] dual source (chunks 0-15 x, 16-31 mln)
    hmma_gemm<2><<<gW1, 256, SMEM_GEMM>>>(xh, mlnh, w1h, nullptr, nullptr,
                                          nullptr, h1h, nullptr, nullptr,
                                          C2, C2, 16, sC, sC, 1.f);
    // W2 -> f32 M2
    hmma_gemm<0><<<gP, 256, SMEM_GEMM>>>(h1h, h1h, w2h, nullptr, nullptr,
                                         pM2, nullptr, nullptr, nullptr,
                                         CC, C2, 9999, sC2, sC2, 1.f);
    ln_add_kernel<<<NTOK, 256>>>(x, g2, b2, out);
}

// round 12
// speedup vs baseline: 1.9957x; 1.0086x over previous
#include <cuda_runtime.h>
#include <cuda_fp16.h>
#include <math.h>
#include <stdint.h>

// ---------------------------------------------------------------------------
// Problem constants
// ---------------------------------------------------------------------------
#define NB   4
#define LL   4096
#define SEQS 4096
#define CC   512
#define NH   8
#define HD   64
#define C2   1024
#define NTOK (NB * LL)          // 16384
#define EPS_Z 1e-6f
#define LN_EPS 1e-5f

// ---------------------------------------------------------------------------
// Scratch (device globals; no allocation allowed)
// ---------------------------------------------------------------------------
__device__ __align__(16) float g_KV[NB * NH * HD * HD];
__device__ __align__(16) float g_Ks[NB * NH * HD];

// fp16 buffers
__device__ __align__(16) __half g_Qh[(size_t)NTOK * CC];
__device__ __align__(16) __half g_Kh[(size_t)NTOK * CC];
__device__ __align__(16) __half g_Vh[(size_t)NTOK * CC];
__device__ __align__(16) __half g_xh[(size_t)NTOK * CC];
__device__ __align__(16) __half g_yh[(size_t)NTOK * CC];
__device__ __align__(16) __half g_Wqh[CC * CC];
__device__ __align__(16) __half g_Wkh[CC * CC];
__device__ __align__(16) __half g_Wvh[CC * CC];
__device__ __align__(16) __half g_Wmh[CC * CC];
__device__ __align__(16) __half g_W1h[C2 * C2];
__device__ __align__(16) __half g_W2h[CC * C2];
__device__ __align__(16) __half g_Mh  [(size_t)NTOK * CC];
__device__ __align__(16) __half g_M1h [(size_t)NTOK * CC];
__device__ __align__(16) __half g_M2h [(size_t)NTOK * CC];
__device__ __align__(16) __half g_mlnh[(size_t)NTOK * CC];
__device__ __align__(16) __half g_H1h [(size_t)NTOK * C2];

// ---------------------------------------------------------------------------
// PTX helpers
// ---------------------------------------------------------------------------
__device__ __forceinline__ uint32_t smem_u32(const void* p)
{
    uint32_t a;
    asm("{ .reg .u64 t; cvta.to.shared.u64 t, %1; cvt.u32.u64 %0, t; }"
        : "=r"(a) : "l"(p));
    return a;
}

__device__ __forceinline__ void cpasync16(uint32_t dst, const void* src)
{
    asm volatile("cp.async.cg.shared.global [%0], [%1], 16;"
                 :: "r"(dst), "l"(src) : "memory");
}
__device__ __forceinline__ void cp_commit()
{
    asm volatile("cp.async.commit_group;" ::: "memory");
}
template <int N>
__device__ __forceinline__ void cp_wait()
{
    asm volatile("cp.async.wait_group %0;" :: "n"(N) : "memory");
}

__device__ __forceinline__ void ldm_x4(uint32_t& r0, uint32_t& r1,
                                       uint32_t& r2, uint32_t& r3, uint32_t a)
{
    asm volatile("ldmatrix.sync.aligned.m8n8.x4.shared.b16 {%0,%1,%2,%3}, [%4];"
                 : "=r"(r0), "=r"(r1), "=r"(r2), "=r"(r3) : "r"(a));
}

__device__ __forceinline__ void ldm_x4p(uint32_t* r, uint32_t a)
{
    asm volatile("ldmatrix.sync.aligned.m8n8.x4.shared.b16 {%0,%1,%2,%3}, [%4];"
                 : "=r"(r[0]), "=r"(r[1]), "=r"(r[2]), "=r"(r[3]) : "r"(a));
}

__device__ __forceinline__ void ldm_x4_t(uint32_t* r, uint32_t a)
{
    asm volatile("ldmatrix.sync.aligned.m8n8.x4.trans.shared.b16 {%0,%1,%2,%3}, [%4];"
                 : "=r"(r[0]), "=r"(r[1]), "=r"(r[2]), "=r"(r[3]) : "r"(a));
}

__device__ __forceinline__ void mma16816(float* c, const uint32_t* a,
                                         const uint32_t* b)
{
    asm volatile(
        "mma.sync.aligned.m16n8k16.row.col.f32.f16.f16.f32 "
        "{%0,%1,%2,%3}, {%4,%5,%6,%7}, {%8,%9}, {%0,%1,%2,%3};"
        : "+f"(c[0]), "+f"(c[1]), "+f"(c[2]), "+f"(c[3])
        : "r"(a[0]), "r"(a[1]), "r"(a[2]), "r"(a[3]), "r"(b[0]), "r"(b[1]));
}

// ---------------------------------------------------------------------------
// Mega split: fp32 -> fp16
// ---------------------------------------------------------------------------
#define NSPLIT 8
struct SplitJobs {
    const float* src[NSPLIT];
    __half* hi[NSPLIT];
    int n4[NSPLIT];
    int blkoff[NSPLIT + 1];
};

__global__ void __launch_bounds__(256)
split_all(SplitJobs J)
{
    int b = blockIdx.x;
    int j = 0;
#pragma unroll
    for (int t = 0; t < NSPLIT - 1; t++)
        if (b >= J.blkoff[t + 1]) j = t + 1;
    const int i = (b - J.blkoff[j]) * 256 + threadIdx.x;
    if (i >= J.n4[j]) return;
    float4 v = ((const float4*)J.src[j])[i];
    ((__half2*)J.hi[j])[i * 2 + 0] =
        __half2(__float2half_rn(v.x), __float2half_rn(v.y));
    ((__half2*)J.hi[j])[i * 2 + 1] =
        __half2(__float2half_rn(v.z), __float2half_rn(v.w));
}

// ---------------------------------------------------------------------------
// fp16 1-pass HMMA GEMM. Tile 128x128, BK=32 fp32-K, 4-stage cp.async,
// 8 warps 2x4, dual A-source (kSplit). EPI:
//   2 = relu -> fp16 Ch
//   4 = merged QKV: seg=bx>>2: 0 -> elu(A1@Bh)->Ch, 1 -> elu(A2@B2h)->Ch2,
//                   2 -> (A2@B3h)*scale -> Ch3
//   5 = *scale -> fp16 Ch
// ---------------------------------------------------------------------------
#define ROWB   80
#define MATB   (128 * ROWB)       // 10240 B
#define STAGEB (2 * MATB)         // 20480 B (Ah, Bh)
#define NSTG   4
#define SMEM_GEMM (NSTG * STAGEB) // 81920 B

template <int EPI>
__global__ void __launch_bounds__(256, 2)
hmma_gemm(const __half* __restrict__ A1h, const __half* __restrict__ A2h,
          const __half* __restrict__ Bh, const __half* __restrict__ B2h,
          const __half* __restrict__ B3h,
          __half* __restrict__ Ch, __half* __restrict__ Ch2,
          __half* __restrict__ Ch3,
          int N, int K, int kSplit,
          size_t sA1b, size_t sA2b, float scale)
{
    extern __shared__ __align__(16) uint8_t dynsm[];
    const uint32_t sbase = smem_u32(dynsm);

    const int tid  = threadIdx.x;
    const int wid  = tid >> 5;
    const int lane = tid & 31;
    const int wr   = wid >> 2;
    const int wc   = wid & 3;
    const int bx   = blockIdx.x;
    const int by   = blockIdx.y;

    const int seg = (EPI == 4) ? (bx >> 2) : 0;
    const int bn  = (EPI == 4) ? (bx & 3) : bx;
    const __half* Bsel = Bh;
    if (EPI == 4) Bsel = (seg == 0) ? Bh : ((seg == 1) ? B2h : B3h);
    const int kS = (EPI == 4) ? ((seg == 0) ? 9999 : 0) : kSplit;

    const int row0 = tid >> 2;               // 0..63
    const int cb   = (tid & 3) * 16;
    const size_t sBb = (size_t)K * 2;

    const char* gA1h = (const char*)A1h + (size_t)(by * 128 + row0) * sA1b + cb;
    const char* gA2h = (const char*)A2h + (size_t)(by * 128 + row0) * sA2b + cb;
    const char* gBh0 = (const char*)Bsel + (size_t)(bn * 128 + row0) * sBb + cb;
    const size_t rs1 = 64 * sA1b, rs2 = 64 * sA2b, rsB = 64 * sBb;

    const uint32_t dA0 = (uint32_t)(row0 * ROWB + cb);
    const uint32_t dA1 = (uint32_t)((row0 + 64) * ROWB + cb);

    auto issue = [&](int stage, int chunk) {
        const uint32_t s = sbase + stage * STAGEB;
        const char *ah; size_t o, rs;
        if (chunk < kS) { ah = gA1h; o = (size_t)chunk * 64; rs = rs1; }
        else { ah = gA2h; o = (size_t)(chunk - kS) * 64; rs = rs2; }
        cpasync16(s + dA0, ah + o);
        cpasync16(s + dA1, ah + o + rs);
        const size_t ob = (size_t)chunk * 64;
        cpasync16(s + MATB + dA0, gBh0 + ob);
        cpasync16(s + MATB + dA1, gBh0 + ob + rsB);
        cp_commit();
    };

    const uint32_t aRow = (uint32_t)(wr * 64 + (lane & 15));
    const uint32_t aCol = (uint32_t)((lane >> 4) << 4);
    const uint32_t bRow = (uint32_t)(wc * 32 + (lane & 7) + ((lane >> 4) << 3));
    const uint32_t bCol = (uint32_t)(((lane >> 3) & 1) << 4);

    float acc[4][4][4];
#pragma unroll
    for (int i = 0; i < 4; i++)
#pragma unroll
        for (int j = 0; j < 4; j++)
#pragma unroll
            for (int q = 0; q < 4; q++) acc[i][j][q] = 0.f;

    const int nch = K / 32;
    issue(0, 0);
    if (nch > 1) issue(1, 1);

    for (int c = 0; c < nch; c++) {
        if (c + 2 < nch) { issue((c + 2) % NSTG, c + 2); cp_wait<2>(); }
        else if (c + 1 < nch) { cp_wait<1>(); }
        else { cp_wait<0>(); }
        __syncthreads();

        const uint32_t s  = sbase + (c % NSTG) * STAGEB;
        const uint32_t pAh = s, pBh = s + MATB;

#pragma unroll
        for (int ks = 0; ks < 2; ks++) {
            const uint32_t kb = (uint32_t)(ks * 32);

            uint32_t ah[4][4], bh[2][4];
#pragma unroll
            for (int mi = 0; mi < 4; mi++)
                ldm_x4(ah[mi][0], ah[mi][1], ah[mi][2], ah[mi][3],
                       pAh + (aRow + mi * 16) * ROWB + kb + aCol);
#pragma unroll
            for (int ng = 0; ng < 2; ng++)
                ldm_x4(bh[ng][0], bh[ng][1], bh[ng][2], bh[ng][3],
                       pBh + (bRow + ng * 16) * ROWB + kb + bCol);
#pragma unroll
            for (int mi = 0; mi < 4; mi++)
#pragma unroll
                for (int ni = 0; ni < 4; ni++)
                    mma16816(acc[mi][ni], ah[mi], &bh[ni >> 1][(ni & 1) * 2]);
        }
        __syncthreads();
    }

    // ---- epilogue
#pragma unroll
    for (int mi = 0; mi < 4; mi++) {
#pragma unroll
        for (int ni = 0; ni < 4; ni++) {
            const int r = by * 128 + wr * 64 + mi * 16 + (lane >> 2);
            const int cn = bn * 128 + wc * 32 + ni * 8 + (lane & 3) * 2;
            float v0 = acc[mi][ni][0];
            float v1 = acc[mi][ni][1];
            float v2 = acc[mi][ni][2];
            float v3 = acc[mi][ni][3];
            if (EPI == 5 || (EPI == 4 && seg == 2)) {
                v0 *= scale; v1 *= scale; v2 *= scale; v3 *= scale;
            }
            if (EPI == 4 && seg < 2) {
                v0 = (v0 > 0.f) ? (v0 + 1.f) : expf(v0);
                v1 = (v1 > 0.f) ? (v1 + 1.f) : expf(v1);
                v2 = (v2 > 0.f) ? (v2 + 1.f) : expf(v2);
                v3 = (v3 > 0.f) ? (v3 + 1.f) : expf(v3);
            }
            if (EPI == 2) {
                v0 = fmaxf(v0, 0.f); v1 = fmaxf(v1, 0.f);
                v2 = fmaxf(v2, 0.f); v3 = fmaxf(v3, 0.f);
            }

            __half* outp = Ch;
            if (EPI == 4) outp = (seg == 0) ? Ch : ((seg == 1) ? Ch2 : Ch3);
            *(__half2*)(outp + (size_t)r * N + cn) =
                __half2(__float2half_rn(v0), __float2half_rn(v1));
            *(__half2*)(outp + (size_t)(r + 8) * N + cn) =
                __half2(__float2half_rn(v2), __float2half_rn(v3));
        }
    }
}

// ---------------------------------------------------------------------------
// Zero KV / Ksum accumulators
// ---------------------------------------------------------------------------
__global__ void zero_kv_kernel()
{
    int i = blockIdx.x * blockDim.x + threadIdx.x;
    if (i < NB * NH * HD * HD) g_KV[i] = 0.f;
    if (i < NB * NH * HD)      g_Ks[i] = 0.f;
}

// ---------------------------------------------------------------------------
// KV via tensor cores: KV[n,h] = K^T @ V (+ Ksum) over this block's s-range.
// ---------------------------------------------------------------------------
#define KV_SPLIT 16
#define KROWB  144
#define KTILEB (64 * KROWB)

__global__ void __launch_bounds__(256)
kv_kernel()
{
    __shared__ __align__(16) uint8_t sm[4 * KTILEB];   // K0,V0,K1,V1
    const uint32_t sbase = smem_u32(sm);

    const int n = blockIdx.z, h = blockIdx.y, sp = blockIdx.x;
    const int s0 = sp * (SEQS / KV_SPLIT);
    const int tid  = threadIdx.x;
    const int wid  = tid >> 5;
    const int lane = tid & 31;
    const int d0   = (wid & 3) * 16;
    const int v0   = (wid >> 2) * 32;

    const char* gK = (const char*)g_Kh + ((size_t)(n * SEQS + s0) * CC + h * HD) * 2;
    const char* gV = (const char*)g_Vh + ((size_t)(n * SEQS + s0) * CC + h * HD) * 2;

    auto issue = [&](int stage, int chunk) {
        const uint32_t sK = sbase + stage * 2 * KTILEB;
        const uint32_t sV = sK + KTILEB;
        const size_t goff = (size_t)chunk * 64 * CC * 2;
#pragma unroll
        for (int i = 0; i < 2; i++) {
            const int slot = tid + i * 256;
            const int r  = slot >> 3;
            const int cc = (slot & 7) * 16;
            cpasync16(sK + r * KROWB + cc, gK + goff + (size_t)r * CC * 2 + cc);
            cpasync16(sV + r * KROWB + cc, gV + goff + (size_t)r * CC * 2 + cc);
        }
        cp_commit();
    };

    const uint32_t aRow = (uint32_t)(((lane >> 4) << 3) + (lane & 7));
    const uint32_t aCol = (uint32_t)((d0 + ((lane >> 3) & 1) * 8) * 2);
    const uint32_t bRow = (uint32_t)((((lane >> 3) & 1) << 3) + (lane & 7));
    const uint32_t bColBase = (uint32_t)((v0 + (lane >> 4) * 8) * 2);

    float acc[4][4];
#pragma unroll
    for (int i = 0; i < 4; i++)
#pragma unroll
        for (int q = 0; q < 4; q++) acc[i][q] = 0.f;
    float ksacc = 0.f;

    issue(0, 0);
    const int nch = (SEQS / KV_SPLIT) / 64;

    for (int c = 0; c < nch; c++) {
        cp_wait<0>();
        __syncthreads();
        if (c + 1 < nch) issue((c + 1) & 1, c + 1);

        const uint32_t sK = sbase + (c & 1) * 2 * KTILEB;
        const uint32_t sV = sK + KTILEB;

#pragma unroll
        for (int ks = 0; ks < 4; ks++) {
            const uint32_t srow = (uint32_t)(ks * 16);
            uint32_t a[4], b0[4], b1[4];
            ldm_x4_t(a,  sK + (srow + aRow) * KROWB + aCol);
            ldm_x4_t(b0, sV + (srow + bRow) * KROWB + bColBase);
            ldm_x4_t(b1, sV + (srow + bRow) * KROWB + bColBase + 32);
            mma16816(acc[0], a, &b0[0]);
            mma16816(acc[1], a, &b0[2]);
            mma16816(acc[2], a, &b1[0]);
            mma16816(acc[3], a, &b1[2]);
        }

        if (tid < HD) {
            const uint32_t boff = (c & 1) * 2 * KTILEB + (uint32_t)(tid * 2);
#pragma unroll 8
            for (int s = 0; s < 64; s++)
                ksacc += __half2float(*(const __half*)(sm + boff + s * KROWB));
        }
        __syncthreads();
    }

    float* KVp = g_KV + (size_t)(n * NH + h) * HD * HD;
    const int dr = d0 + (lane >> 2);
    const int vc = (lane & 3) * 2;
#pragma unroll
    for (int ni = 0; ni < 4; ni++) {
        const int v = v0 + ni * 8 + vc;
        atomicAdd(&KVp[(size_t)dr * HD + v],           acc[ni][0]);
        atomicAdd(&KVp[(size_t)dr * HD + v + 1],       acc[ni][1]);
        atomicAdd(&KVp[(size_t)(dr + 8) * HD + v],     acc[ni][2]);
        atomicAdd(&KVp[(size_t)(dr + 8) * HD + v + 1], acc[ni][3]);
    }
    if (tid < HD)
        atomicAdd(&g_Ks[(n * NH + h) * HD + tid], ksacc);
}

// ---------------------------------------------------------------------------
// msg via tensor cores: per (n,h,128-l-tile):
//   M[l, h*64+v] = S * (Q[l,:] @ KV[:,v]) / (Q[l,:] . Ksum + eps)
// KV fp32 converted to smem fp16 [d][v] in-kernel; B via ldmatrix.trans.
// 128 threads (4 warps, 32 rows each).
// ---------------------------------------------------------------------------
#define MROWB 144
__global__ void __launch_bounds__(128)
msg_tc_kernel()
{
    __shared__ __align__(16) uint8_t smQ[128 * MROWB];
    __shared__ __align__(16) uint8_t smB[64 * MROWB];   // KV fp16, rows=d cols=v
    __shared__ float Kss[HD];

    const int n = blockIdx.z, h = blockIdx.y, lt = blockIdx.x;
    const int tid  = threadIdx.x;
    const int wr   = tid >> 5;
    const int lane = tid & 31;

    const uint32_t sQ = smem_u32(smQ);
    const uint32_t sB = smem_u32(smB);

    const char* gQ = (const char*)g_Qh +
        ((size_t)(n * LL + lt * 128) * CC + h * HD) * 2;
    const float* gKV = g_KV + (size_t)(n * NH + h) * HD * HD;

    // async load Q tile: 128 rows x 128B
#pragma unroll
    for (int i = 0; i < 8; i++) {
        const int slot = tid + i * 128;
        const int r = slot >> 3, c = (slot & 7) * 16;
        cpasync16(sQ + r * MROWB + c, gQ + (size_t)r * CC * 2 + c);
    }
    cp_commit();

    // convert KV fp32 -> smem fp16 (overlaps with Q cp.async)
#pragma unroll
    for (int i = 0; i < 32; i++) {
        const int idx = tid + i * 128;          // 0..4095
        const int d = idx >> 6, v = idx & 63;
        *(__half*)(smB + d * MROWB + v * 2) = __float2half_rn(gKV[idx]);
    }
    if (tid < HD) Kss[tid] = g_Ks[(n * NH + h) * HD + tid];
    cp_wait<0>();
    __syncthreads();

    const uint32_t aRow = (uint32_t)(wr * 32 + (lane & 15));
    const uint32_t aCol = (uint32_t)((lane >> 4) << 4);
    // B (trans): rows = k(d), cols = v
    const uint32_t bRow = (uint32_t)((((lane >> 3) & 1) << 3) + (lane & 7));
    const uint32_t bColB = (uint32_t)((lane >> 4) << 4);   // (lane>>4)*8 halves

    float acc[2][8][4];
#pragma unroll
    for (int i = 0; i < 2; i++)
#pragma unroll
        for (int j = 0; j < 8; j++)
#pragma unroll
            for (int q = 0; q < 4; q++) acc[i][j][q] = 0.f;

#pragma unroll
    for (int ks = 0; ks < 4; ks++) {
        const uint32_t kb = (uint32_t)(ks * 32);
        uint32_t a[2][4], b[4][4];
#pragma unroll
        for (int mi = 0; mi < 2; mi++)
            ldm_x4p(a[mi], sQ + (aRow + mi * 16) * MROWB + kb + aCol);
#pragma unroll
        for (int g = 0; g < 4; g++)
            ldm_x4_t(b[g], sB + (ks * 16 + bRow) * MROWB + bColB + g * 32);
#pragma unroll
        for (int mi = 0; mi < 2; mi++)
#pragma unroll
            for (int ni = 0; ni < 8; ni++)
                mma16816(acc[mi][ni], a[mi], &b[ni >> 1][(ni & 1) * 2]);
    }

    // epilogue: per-row zden then scaled fp16 store
#pragma unroll
    for (int mi = 0; mi < 2; mi++) {
        const int r0 = wr * 32 + mi * 16 + (lane >> 2);
        float zd0 = EPS_Z, zd1 = EPS_Z;
        const __half2* q0 = (const __half2*)(smQ + r0 * MROWB);
        const __half2* q1 = (const __half2*)(smQ + (r0 + 8) * MROWB);
#pragma unroll
        for (int k = 0; k < HD / 2; k++) {
            const float2 a0 = __half22float2(q0[k]);
            const float2 a1 = __half22float2(q1[k]);
            zd0 = fmaf(a0.x, Kss[2 * k], fmaf(a0.y, Kss[2 * k + 1], zd0));
            zd1 = fmaf(a1.x, Kss[2 * k], fmaf(a1.y, Kss[2 * k + 1], zd1));
        }
        const float zs0 = (float)SEQS / zd0;
        const float zs1 = (float)SEQS / zd1;

        const size_t base0 = ((size_t)(n * LL + lt * 128 + r0)) * CC + h * HD;
        const size_t base1 = base0 + (size_t)8 * CC;
#pragma unroll
        for (int ni = 0; ni < 8; ni++) {
            const int cn = ni * 8 + (lane & 3) * 2;
            *(__half2*)(g_Mh + base0 + cn) =
                __half2(__float2half_rn(acc[mi][ni][0] * zs0),
                        __float2half_rn(acc[mi][ni][1] * zs0));
            *(__half2*)(g_Mh + base1 + cn) =
                __half2(__float2half_rn(acc[mi][ni][2] * zs1),
                        __float2half_rn(acc[mi][ni][3] * zs1));
        }
    }
}

// ---------------------------------------------------------------------------
// Block reduction helper (256 threads)
// ---------------------------------------------------------------------------
__device__ __forceinline__ float block_reduce_sum(float v)
{
    __shared__ float red[8];
    const int lane = threadIdx.x & 31, w = threadIdx.x >> 5;
#pragma unroll
    for (int o = 16; o; o >>= 1) v += __shfl_down_sync(0xffffffffu, v, o);
    if (lane == 0) red[w] = v;
    __syncthreads();
    float t = (threadIdx.x < 8) ? red[threadIdx.x] : 0.f;
    if (w == 0) {
#pragma unroll
        for (int o = 4; o; o >>= 1) t += __shfl_down_sync(0xffu, t, o);
        if (lane == 0) red[0] = t;
    }
    __syncthreads();
    float r = red[0];
    __syncthreads();
    return r;
}

// ---------------------------------------------------------------------------
// LN(M1 fp16) -> fp16 (message half of the concat). One block per row.
// ---------------------------------------------------------------------------
__global__ void __launch_bounds__(256)
ln_split_kernel(const float* __restrict__ g, const float* __restrict__ b)
{
    const int row = blockIdx.x;
    __shared__ float buf[CC];
    const __half* mr = g_M1h + (size_t)row * CC;
    const int tid = threadIdx.x;

    float s = 0.f;
    for (int c = tid; c < CC; c += 256) {
        float v = __half2float(mr[c]); buf[c] = v; s += v;
    }
    const float mean = block_reduce_sum(s) * (1.f / CC);

    float vs = 0.f;
    for (int c = tid; c < CC; c += 256) { float d = buf[c] - mean; vs += d * d; }
    const float var  = block_reduce_sum(vs) * (1.f / CC);
    const float rstd = rsqrtf(var + LN_EPS);

    for (int c = tid; c < CC; c += 256) {
        const float lv = (buf[c] - mean) * rstd * g[c] + b[c];
        g_mlnh[(size_t)row * CC + c] = __float2half_rn(lv);
    }
}

// ---------------------------------------------------------------------------
// out = x + LN(M2 fp16). One block per row.
// ---------------------------------------------------------------------------
__global__ void __launch_bounds__(256)
ln_add_kernel(const float* __restrict__ x,
              const float* __restrict__ g, const float* __restrict__ b,
              float* __restrict__ out)
{
    const int row = blockIdx.x;
    __shared__ float buf[CC];
    const __half* mr = g_M2h + (size_t)row * CC;
    const int tid = threadIdx.x;

    float s = 0.f;
    for (int c = tid; c < CC; c += 256) {
        float v = __half2float(mr[c]); buf[c] = v; s += v;
    }
    const float mean = block_reduce_sum(s) * (1.f / CC);

    float vs = 0.f;
    for (int c = tid; c < CC; c += 256) { float d = buf[c] - mean; vs += d * d; }
    const float var  = block_reduce_sum(vs) * (1.f / CC);
    const float rstd = rsqrtf(var + LN_EPS);

    for (int c = tid; c < CC; c += 256) {
        out[(size_t)row * CC + c] =
            x[(size_t)row * CC + c] + (buf[c] - mean) * rstd * g[c] + b[c];
    }
}

// ---------------------------------------------------------------------------
// Launcher
// ---------------------------------------------------------------------------
extern "C" void kernel_launch(void* const* d_in, const int* in_sizes, int n_in,
                              void* d_out, int out_size)
{
    const float* x  = (const float*)d_in[0];
    const float* y  = (const float*)d_in[1];
    const float* Wq = (const float*)d_in[2];
    const float* Wk = (const float*)d_in[3];
    const float* Wv = (const float*)d_in[4];
    const float* Wm = (const float*)d_in[5];
    const float* W1 = (const float*)d_in[6];
    const float* W2 = (const float*)d_in[7];
    const float* g1 = (const float*)d_in[8];
    const float* b1 = (const float*)d_in[9];
    const float* g2 = (const float*)d_in[10];
    const float* b2 = (const float*)d_in[11];
    float* out = (float*)d_out;

    __half *qh,*kh,*vh,*xh,*yh,*wqh,*wkh,*wvh,*wmh,*w1h,*w2h;
    __half *mh,*m1h,*m2h,*mlnh,*h1h;
    cudaGetSymbolAddress((void**)&qh,  g_Qh);
    cudaGetSymbolAddress((void**)&kh,  g_Kh);
    cudaGetSymbolAddress((void**)&vh,  g_Vh);
    cudaGetSymbolAddress((void**)&xh,  g_xh);
    cudaGetSymbolAddress((void**)&yh,  g_yh);
    cudaGetSymbolAddress((void**)&wqh, g_Wqh);
    cudaGetSymbolAddress((void**)&wkh, g_Wkh);
    cudaGetSymbolAddress((void**)&wvh, g_Wvh);
    cudaGetSymbolAddress((void**)&wmh, g_Wmh);
    cudaGetSymbolAddress((void**)&w1h, g_W1h);
    cudaGetSymbolAddress((void**)&w2h, g_W2h);
    cudaGetSymbolAddress((void**)&mh,  g_Mh);
    cudaGetSymbolAddress((void**)&m1h, g_M1h);
    cudaGetSymbolAddress((void**)&m2h, g_M2h);
    cudaGetSymbolAddress((void**)&mlnh,g_mlnh);
    cudaGetSymbolAddress((void**)&h1h, g_H1h);

    cudaFuncSetAttribute(hmma_gemm<2>, cudaFuncAttributeMaxDynamicSharedMemorySize, SMEM_GEMM);
    cudaFuncSetAttribute(hmma_gemm<4>, cudaFuncAttributeMaxDynamicSharedMemorySize, SMEM_GEMM);
    cudaFuncSetAttribute(hmma_gemm<5>, cudaFuncAttributeMaxDynamicSharedMemorySize, SMEM_GEMM);

    // ---- one mega split launch
    SplitJobs J;
    const float* srcs[NSPLIT] = {x, y, Wq, Wk, Wv, Wm, W1, W2};
    __half* his[NSPLIT] = {xh, yh, wqh, wkh, wvh, wmh, w1h, w2h};
    const int n4s[NSPLIT] = {NTOK * CC / 4, NTOK * CC / 4, CC * CC / 4, CC * CC / 4,
                             CC * CC / 4, CC * CC / 4, C2 * C2 / 4, CC * C2 / 4};
    int off = 0;
    for (int j = 0; j < NSPLIT; j++) {
        J.src[j] = srcs[j]; J.hi[j] = his[j]; J.n4[j] = n4s[j];
        J.blkoff[j] = off;
        off += (n4s[j] + 255) / 256;
    }
    J.blkoff[NSPLIT] = off;
    split_all<<<off, 256>>>(J);

    const dim3 gQKV(3 * CC / 128, NTOK / 128);  // 12 x 128 (Q, K, V)
    const dim3 gP  (CC / 128, NTOK / 128);      // 4 x 128
    const dim3 gW1 (C2 / 128, NTOK / 128);      // 8 x 128
    const size_t sC = (size_t)CC * 2, sC2 = (size_t)C2 * 2;

    // merged Q,K,V projections
    hmma_gemm<4><<<gQKV, 256, SMEM_GEMM>>>(xh, yh, wqh, wkh, wvh,
                                           qh, kh, vh, CC, CC, 9999,
                                           sC, sC, 1.f / (float)SEQS);

    zero_kv_kernel<<<(NB * NH * HD * HD + 255) / 256, 256>>>();
    kv_kernel<<<dim3(KV_SPLIT, NH, NB), 256>>>();
    msg_tc_kernel<<<dim3(LL / 128, NH, NB), 128>>>();

    // Wm: fp16 message -> fp16 M1
    hmma_gemm<5><<<gP, 256, SMEM_GEMM>>>(mh, mh, wmh, nullptr, nullptr,
                                         m1h, nullptr, nullptr,
                                         CC, CC, 9999, sC, sC, 1.f);
    ln_split_kernel<<<NTOK, 256>>>(g1, b1);
    // W1: relu -> fp16; A = [x | LN(msg)] dual source (chunks 0-15 x, 16-31 mln)
    hmma_gemm<2><<<gW1, 256, SMEM_GEMM>>>(xh, mlnh, w1h, nullptr, nullptr,
                                          h1h, nullptr, nullptr,
                                          C2, C2, 16, sC, sC, 1.f);
    // W2 -> fp16 M2
    hmma_gemm<5><<<gP, 256, SMEM_GEMM>>>(h1h, h1h, w2h, nullptr, nullptr,
                                         m2h, nullptr, nullptr,
                                         CC, C2, 9999, sC2, sC2, 1.f);
    ln_add_kernel<<<NTOK, 256>>>(x, g2, b2, out);
}